// round 12
// baseline (speedup 1.0000x reference)
#include <cuda_runtime.h>
#include <cuda_bf16.h>
#include <cstdint>

// ============================================================================
// Problem constants
// ============================================================================
#define S_LEN   2048
#define EMBED   1024
#define E3      3072
#define HEADS   16
#define HDIM    64
#define BATCH   4
#define M_TOTAL (BATCH * S_LEN) /* 8192 */

// Scratch (allocation-free contract)
__device__ __align__(16) __nv_bfloat16 g_qkvh[(size_t)M_TOTAL * E3];
__device__ __align__(16) __nv_bfloat16 g_qkvl[(size_t)M_TOTAL * E3];
__device__ float g_attn[(size_t)M_TOTAL * EMBED];
__device__ __align__(16) __nv_bfloat16 g_wq_hi[(size_t)E3 * EMBED];
__device__ __align__(16) __nv_bfloat16 g_wq_lo[(size_t)E3 * EMBED];
__device__ __align__(16) __nv_bfloat16 g_wo_hi[(size_t)EMBED * EMBED];
__device__ __align__(16) __nv_bfloat16 g_wo_lo[(size_t)EMBED * EMBED];

// ============================================================================
// Helpers
// ============================================================================
__device__ __forceinline__ uint32_t smem_to_u32(const void* smem_ptr) {
    uint32_t addr;
    asm("{ .reg .u64 tmp; cvta.to.shared.u64 tmp, %1; cvt.u32.u64 %0, tmp; }"
        : "=r"(addr) : "l"(smem_ptr));
    return addr;
}

#define SMEM_SWIZZLE_128B(byte_offset) \
    ((byte_offset) ^ (((byte_offset) >> 3) & 0x70))

__device__ __forceinline__ void ldsm4(uint32_t addr, uint32_t r[4]) {
    asm volatile("ldmatrix.sync.aligned.m8n8.x4.shared.b16 {%0,%1,%2,%3}, [%4];"
                 : "=r"(r[0]), "=r"(r[1]), "=r"(r[2]), "=r"(r[3]) : "r"(addr));
}

__device__ __forceinline__ void ldsm4t(uint32_t addr, uint32_t r[4]) {
    asm volatile("ldmatrix.sync.aligned.m8n8.x4.trans.shared.b16 {%0,%1,%2,%3}, [%4];"
                 : "=r"(r[0]), "=r"(r[1]), "=r"(r[2]), "=r"(r[3]) : "r"(addr));
}

__device__ __forceinline__ void mma16816(float c[4], const uint32_t a[4],
                                         uint32_t b0, uint32_t b1) {
    asm volatile(
        "mma.sync.aligned.m16n8k16.row.col.f32.bf16.bf16.f32 "
        "{%0,%1,%2,%3}, {%4,%5,%6,%7}, {%8,%9}, {%0,%1,%2,%3};"
        : "+f"(c[0]), "+f"(c[1]), "+f"(c[2]), "+f"(c[3])
        : "r"(a[0]), "r"(a[1]), "r"(a[2]), "r"(a[3]), "r"(b0), "r"(b1));
}

__device__ __forceinline__ void cp_async16(uint32_t saddr, const void* gptr) {
    asm volatile("cp.async.cg.shared.global [%0], [%1], 16;"
                 :: "r"(saddr), "l"(gptr) : "memory");
}
#define CP_COMMIT() asm volatile("cp.async.commit_group;" ::: "memory")

__device__ __forceinline__ void split_bf16(float v, __nv_bfloat16& h, __nv_bfloat16& l) {
    h = __float2bfloat16(v);
    l = __float2bfloat16(v - __bfloat162float(h));
}

__device__ __forceinline__ uint32_t pack_bf16(__nv_bfloat16 a, __nv_bfloat16 b) {
    __nv_bfloat162 t = __halves2bfloat162(a, b);
    return *reinterpret_cast<uint32_t*>(&t);
}

// pack (x,y) -> bf16x2 hi-word, residual pair -> lo-word
__device__ __forceinline__ void pack_split(float x, float y, uint32_t& hp, uint32_t& lp) {
    asm("cvt.rn.bf16x2.f32 %0, %1, %2;" : "=r"(hp) : "f"(y), "f"(x));
    const float hx = __uint_as_float(hp << 16);
    const float hy = __uint_as_float(hp & 0xffff0000u);
    const float rx = x - hx, ry = y - hy;
    asm("cvt.rn.bf16x2.f32 %0, %1, %2;" : "=r"(lp) : "f"(ry), "f"(rx));
}

// ============================================================================
// Prep: transpose W[K,N] -> Wt[N,K], split fp32 into bf16 hi + lo
// ============================================================================
__global__ __launch_bounds__(256)
void wtrans_split_kernel(const float* __restrict__ W, __nv_bfloat16* __restrict__ Th,
                         __nv_bfloat16* __restrict__ Tl, int K, int N) {
    __shared__ float t[32][33];
    const int n0 = blockIdx.x * 32, k0 = blockIdx.y * 32;
    const int tid = threadIdx.x;
    const int c = tid & 31, r = tid >> 5;
#pragma unroll
    for (int i = 0; i < 4; i++)
        t[r + i * 8][c] = W[(size_t)(k0 + r + i * 8) * N + n0 + c];
    __syncthreads();
    const int n  = tid >> 3;
    const int kq = (tid & 7) * 4;
    __nv_bfloat16 h[4], l[4];
#pragma unroll
    for (int j = 0; j < 4; j++) split_bf16(t[kq + j][n], h[j], l[j]);
    const size_t o = (size_t)(n0 + n) * K + k0 + kq;
    *(__nv_bfloat162*)&Th[o]     = __halves2bfloat162(h[0], h[1]);
    *(__nv_bfloat162*)&Th[o + 2] = __halves2bfloat162(h[2], h[3]);
    *(__nv_bfloat162*)&Tl[o]     = __halves2bfloat162(l[0], l[1]);
    *(__nv_bfloat162*)&Tl[o + 2] = __halves2bfloat162(l[2], l[3]);
}

// ============================================================================
// HMMA GEMM, 2-CTA/SM with the measured-best 64x32 warp tile:
// CTA = 128 threads (4 warps, 2x2), tile 128(M) x 64(N), BK=64.
// A fp32 input, register gmem prefetch + in-kernel split (r4 producer),
// double-buffered smem: 2 x 48KB = 96KB -> 2 CTAs/SM, 256-reg budget.
// ============================================================================
#define BM 128
#define BN 64
#define BK 64
#define A_TILE 16384            /* 128 rows x 128B, per h/l */
#define B_TILE 8192             /* 64 rows x 128B, per h/l */
#define OFF_AH 0
#define OFF_AL A_TILE
#define OFF_BH (2 * A_TILE)
#define OFF_BL (2 * A_TILE + B_TILE)
#define STAGE_SZ  (2 * A_TILE + 2 * B_TILE)   /* 49152 */
#define SM_GEMM_TOTAL (2 * STAGE_SZ)          /* 98304 */

__global__ __launch_bounds__(128, 2)
void tc_gemm_bias(const float* __restrict__ A, const __nv_bfloat16* __restrict__ Bth,
                  const __nv_bfloat16* __restrict__ Btl, const float* __restrict__ bias,
                  float* __restrict__ Cf, __nv_bfloat16* __restrict__ Ch,
                  __nv_bfloat16* __restrict__ Cl,
                  int M, int N, int K, int scale_cols) {
    extern __shared__ char smem[];
    __shared__ float sbias[BN];
    const uint32_t sb = smem_to_u32(smem);
    const int tid  = threadIdx.x;
    const int wid  = tid >> 5;
    const int lane = tid & 31;
    const int row0 = blockIdx.y * BM;
    const int col0 = blockIdx.x * BN;
    const int nchunks = K / BK;

    if (tid < BN) sbias[tid] = bias[col0 + tid];

    // ---- producer: thread owns A row `tid` (full 64 fp32 per chunk, split
    //      into hi/lo) and B row `tid>>1` half-row (hi for even tid... ) ----
    const float* arow = A + (size_t)(row0 + tid) * K;
    // B: 64 rows x (hi,lo). Combined row id = tid: tid<64 -> Bh row tid,
    //    tid>=64 -> Bl row tid-64. Each thread owns a full 128B row.
    const __nv_bfloat16* brow = (tid < 64) ? (Bth + (size_t)(col0 + tid) * K)
                                           : (Btl + (size_t)(col0 + (tid - 64)) * K);
    const uint32_t b_base = (uint32_t)((tid < 64 ? OFF_BH : OFF_BL) + (tid & 63) * 128);
    const uint32_t b_sw   = ((uint32_t)tid & 7) << 4;
    const uint32_t a_base = (uint32_t)(tid * 128);
    const uint32_t a_sw   = ((uint32_t)tid & 7) << 4;

    // consumer addressing: 2x2 warp grid, warp tile 64x32 (r4-identical)
    const int wm = (wid >> 1) * 64;
    const int wn = (wid & 1) * 32;
    const int a_r    = lane & 15;
    const int a_half = lane >> 4;
    const int b_nr   = (lane & 7) | ((lane >> 4) << 3);
    const int b_kh   = (lane >> 3) & 1;

    uint32_t a_rowoff[4], a_xor[4], b_rowoff[2], b_xor[2];
#pragma unroll
    for (int i = 0; i < 4; i++) {
        const int r = wm + i * 16 + a_r;
        a_rowoff[i] = (uint32_t)(r * 128);
        a_xor[i]    = (uint32_t)((r & 7) << 4);
    }
#pragma unroll
    for (int jp = 0; jp < 2; jp++) {
        const int r = wn + jp * 16 + b_nr;
        b_rowoff[jp] = (uint32_t)(r * 128);
        b_xor[jp]    = (uint32_t)((r & 7) << 4);
    }
    const uint32_t a_kbb = (uint32_t)(a_half * 16);
    const uint32_t b_kbb = (uint32_t)(b_kh * 16);

    float acc[4][4][4];
#pragma unroll
    for (int i = 0; i < 4; i++)
#pragma unroll
        for (int j = 0; j < 4; j++)
#pragma unroll
            for (int q = 0; q < 4; q++) acc[i][j][q] = 0.f;

    // ---- store helpers ----
    auto store_stage_A = [&](uint32_t st, const float4* pa) {
#pragma unroll
        for (int i = 0; i < 16; i++) {
            __nv_bfloat16 h0, h1, h2, h3, l0, l1, l2, l3;
            split_bf16(pa[i].x, h0, l0); split_bf16(pa[i].y, h1, l1);
            split_bf16(pa[i].z, h2, l2); split_bf16(pa[i].w, h3, l3);
            const uint32_t off = ((uint32_t)(i * 8)) ^ a_sw;
            asm volatile("st.shared.v2.b32 [%0], {%1, %2};"
                :: "r"(st + OFF_AH + a_base + off), "r"(pack_bf16(h0, h1)), "r"(pack_bf16(h2, h3)) : "memory");
            asm volatile("st.shared.v2.b32 [%0], {%1, %2};"
                :: "r"(st + OFF_AL + a_base + off), "r"(pack_bf16(l0, l1)), "r"(pack_bf16(l2, l3)) : "memory");
        }
    };
    auto store_stage_B = [&](uint32_t st, const uint4* pb) {
#pragma unroll
        for (int i = 0; i < 8; i++) {
            const uint32_t off = ((uint32_t)(i * 16)) ^ b_sw;
            asm volatile("st.shared.v4.b32 [%0], {%1, %2, %3, %4};"
                :: "r"(st + b_base + off), "r"(pb[i].x), "r"(pb[i].y), "r"(pb[i].z), "r"(pb[i].w) : "memory");
        }
    };

    // ---- preload chunk 0 into stage 0 ----
    {
        float4 pa[16];
        uint4 pb[8];
#pragma unroll
        for (int i = 0; i < 16; i++) pa[i] = *(const float4*)(arow + i * 4);
#pragma unroll
        for (int i = 0; i < 8; i++)  pb[i] = *(const uint4*)(brow + i * 8);
        store_stage_A(sb, pa);
        store_stage_B(sb, pb);
    }
    __syncthreads();

    for (int c = 0; c < nchunks; c++) {
        const uint32_t st = sb + (uint32_t)(c & 1) * STAGE_SZ;

        // register prefetch of chunk c+1 (overlaps MMAs below)
        float4 pa[16];
        uint4 pb[8];
        const bool more = (c + 1 < nchunks);
        if (more) {
            const int k0n = (c + 1) * BK;
#pragma unroll
            for (int i = 0; i < 16; i++) pa[i] = *(const float4*)(arow + k0n + i * 4);
#pragma unroll
            for (int i = 0; i < 8; i++)  pb[i] = *(const uint4*)(brow + k0n + i * 8);
        }

#pragma unroll
        for (int ks = 0; ks < 4; ks++) {
            const uint32_t kbA = (uint32_t)(ks * 32) + a_kbb;
            const uint32_t kbB = (uint32_t)(ks * 32) + b_kbb;
            uint32_t ah[4][4], al[4][4], bh[2][4], bl[2][4];
#pragma unroll
            for (int i = 0; i < 4; i++) {
                ldsm4(st + OFF_AH + a_rowoff[i] + (kbA ^ a_xor[i]), ah[i]);
                ldsm4(st + OFF_AL + a_rowoff[i] + (kbA ^ a_xor[i]), al[i]);
            }
#pragma unroll
            for (int jp = 0; jp < 2; jp++) {
                ldsm4(st + OFF_BH + b_rowoff[jp] + (kbB ^ b_xor[jp]), bh[jp]);
                ldsm4(st + OFF_BL + b_rowoff[jp] + (kbB ^ b_xor[jp]), bl[jp]);
            }
#pragma unroll
            for (int i = 0; i < 4; i++)
#pragma unroll
                for (int j = 0; j < 4; j++)
                    mma16816(acc[i][j], ah[i], bh[j >> 1][(j & 1) * 2], bh[j >> 1][(j & 1) * 2 + 1]);
#pragma unroll
            for (int i = 0; i < 4; i++)
#pragma unroll
                for (int j = 0; j < 4; j++)
                    mma16816(acc[i][j], ah[i], bl[j >> 1][(j & 1) * 2], bl[j >> 1][(j & 1) * 2 + 1]);
#pragma unroll
            for (int i = 0; i < 4; i++)
#pragma unroll
                for (int j = 0; j < 4; j++)
                    mma16816(acc[i][j], al[i], bh[j >> 1][(j & 1) * 2], bh[j >> 1][(j & 1) * 2 + 1]);
        }
        __syncthreads();

        if (more) {
            const uint32_t stn = sb + (uint32_t)((c + 1) & 1) * STAGE_SZ;
            store_stage_A(stn, pa);
            store_stage_B(stn, pb);
            __syncthreads();
        }
    }

    // ---- epilogue ----
    const int cr  = lane >> 2;
    const int cc2 = (lane & 3) * 2;
#pragma unroll
    for (int i = 0; i < 4; i++) {
#pragma unroll
        for (int j = 0; j < 4; j++) {
            const int col  = wn + j * 8 + cc2;
            const int gcol = col0 + col;
            const int r0 = row0 + wm + i * 16 + cr;
            float v0 = acc[i][j][0] + sbias[col];
            float v1 = acc[i][j][1] + sbias[col + 1];
            float v2 = acc[i][j][2] + sbias[col];
            float v3 = acc[i][j][3] + sbias[col + 1];
            if (gcol < scale_cols) { v0 *= 0.125f; v1 *= 0.125f; v2 *= 0.125f; v3 *= 0.125f; }
            if (Ch) {
                uint32_t hp, lp;
                pack_split(v0, v1, hp, lp);
                *(uint32_t*)&Ch[(size_t)r0 * N + gcol] = hp;
                *(uint32_t*)&Cl[(size_t)r0 * N + gcol] = lp;
                pack_split(v2, v3, hp, lp);
                *(uint32_t*)&Ch[(size_t)(r0 + 8) * N + gcol] = hp;
                *(uint32_t*)&Cl[(size_t)(r0 + 8) * N + gcol] = lp;
            } else {
                *(float2*)&Cf[(size_t)r0 * N + gcol]       = make_float2(v0, v1);
                *(float2*)&Cf[(size_t)(r0 + 8) * N + gcol] = make_float2(v2, v3);
            }
        }
    }
}

// ============================================================================
// HMMA flash attention (round-10 winner, byte-identical). CTA = 128 q-rows x
// (head, batch), 8 warps, K/V tiles 64 rows, double-buffered, 2 CTAs/SM.
// Output fp32 [B,S,E].
// ============================================================================
#define ATT_STAGE 32768
#define ATT_SMEM  (32768 + 2 * ATT_STAGE)  /* 98304 */
#define KT_ROWS   64

__global__ __launch_bounds__(256, 2)
void attn_mma_kernel(const __nv_bfloat16* __restrict__ QKVh,
                     const __nv_bfloat16* __restrict__ QKVl,
                     float* __restrict__ out) {
    extern __shared__ char smem[];
    const uint32_t sb = smem_to_u32(smem);
    const int tid = threadIdx.x, wid = tid >> 5, lane = tid & 31;
    const int qt = blockIdx.x, h = blockIdx.y, b = blockIdx.z;
    const size_t rowbase = (size_t)b * S_LEN;
    const int hcol = h * HDIM;

    const uint32_t sQH = sb, sQL = sb + 16384;

    {
        const int p_r  = tid >> 1;
        const int p_cb = (tid & 1) * 64;
        const size_t grow = (rowbase + qt * 128 + p_r) * E3 + hcol;
#pragma unroll
        for (int i = 0; i < 4; i++) {
            const uint32_t bc  = (uint32_t)(p_cb + i * 16);
            const uint32_t off = (uint32_t)(p_r * 128) + (bc ^ (((uint32_t)p_r & 7) << 4));
            cp_async16(sQH + off, QKVh + grow + (bc >> 1));
            cp_async16(sQL + off, QKVl + grow + (bc >> 1));
        }
    }
    const int q_r  = tid >> 2;
    const int q_cb = (tid & 3) * 32;
    auto issue_kv = [&](int kt) {
        const uint32_t st = sb + 32768 + (uint32_t)(kt & 1) * ATT_STAGE;
        const size_t growK = (rowbase + kt * KT_ROWS + q_r) * E3 + (EMBED + hcol);
        const size_t growV = growK + EMBED;
#pragma unroll
        for (int i = 0; i < 2; i++) {
            const uint32_t bc  = (uint32_t)(q_cb + i * 16);
            const uint32_t off = (uint32_t)(q_r * 128) + (bc ^ (((uint32_t)q_r & 7) << 4));
            cp_async16(st + off,         QKVh + growK + (bc >> 1));
            cp_async16(st + 8192 + off,  QKVl + growK + (bc >> 1));
            cp_async16(st + 16384 + off, QKVh + growV + (bc >> 1));
            cp_async16(st + 24576 + off, QKVl + growV + (bc >> 1));
        }
    };
    issue_kv(0);
    CP_COMMIT();

    const int wm = wid * 16;
    const int a_row = wm + (lane & 15);
    const uint32_t a_rowoff = (uint32_t)(a_row * 128);
    const uint32_t a_xor    = ((uint32_t)a_row & 7) << 4;
    const uint32_t a_kbb    = (uint32_t)((lane >> 4) * 16);
    const int b_nr = (lane & 7) | ((lane >> 4) << 3);
    const uint32_t b_kbb = (uint32_t)(((lane >> 3) & 1) * 16);
    const uint32_t b_xor = ((uint32_t)lane & 7) << 4;
    const int v_r = ((lane >> 3) & 1) * 8 + (lane & 7);
    const uint32_t v_cbb = (uint32_t)((lane >> 4) * 16);
    const uint32_t v_xor = ((uint32_t)lane & 7) << 4;

    float m0 = -1e30f, m1 = -1e30f, l0 = 0.f, l1 = 0.f;
    float o[8][4];
#pragma unroll
    for (int j = 0; j < 8; j++)
#pragma unroll
        for (int q = 0; q < 4; q++) o[j][q] = 0.f;

    for (int kt = 0; kt < S_LEN / KT_ROWS; kt++) {
        const uint32_t st = sb + 32768 + (uint32_t)(kt & 1) * ATT_STAGE;
        if (kt + 1 < S_LEN / KT_ROWS) {
            issue_kv(kt + 1);
            CP_COMMIT();
            asm volatile("cp.async.wait_group 1;" ::: "memory");
        } else {
            asm volatile("cp.async.wait_group 0;" ::: "memory");
        }
        __syncthreads();

        float s[8][4];
#pragma unroll
        for (int j = 0; j < 8; j++)
#pragma unroll
            for (int q = 0; q < 4; q++) s[j][q] = 0.f;

#pragma unroll
        for (int ks = 0; ks < 4; ks++) {
            const uint32_t akb = (uint32_t)(ks * 32) + a_kbb;
            uint32_t qh[4], ql[4];
            ldsm4(sQH + a_rowoff + (akb ^ a_xor), qh);
            ldsm4(sQL + a_rowoff + (akb ^ a_xor), ql);
            const uint32_t kcb = ((uint32_t)(ks * 32) + b_kbb) ^ b_xor;
#pragma unroll
            for (int jp = 0; jp < 4; jp++) {
                const uint32_t roff = (uint32_t)((jp * 16 + b_nr) * 128);
                uint32_t kh[4], kl[4];
                ldsm4(st + roff + kcb, kh);
                ldsm4(st + 8192 + roff + kcb, kl);
                mma16816(s[2 * jp],     qh, kh[0], kh[1]);
                mma16816(s[2 * jp + 1], qh, kh[2], kh[3]);
                mma16816(s[2 * jp],     qh, kl[0], kl[1]);
                mma16816(s[2 * jp + 1], qh, kl[2], kl[3]);
                mma16816(s[2 * jp],     ql, kh[0], kh[1]);
                mma16816(s[2 * jp + 1], ql, kh[2], kh[3]);
            }
        }

        float mx0 = -1e30f, mx1 = -1e30f;
#pragma unroll
        for (int j = 0; j < 8; j++) {
            mx0 = fmaxf(mx0, fmaxf(s[j][0], s[j][1]));
            mx1 = fmaxf(mx1, fmaxf(s[j][2], s[j][3]));
        }
        mx0 = fmaxf(mx0, __shfl_xor_sync(0xffffffffu, mx0, 1));
        mx0 = fmaxf(mx0, __shfl_xor_sync(0xffffffffu, mx0, 2));
        mx1 = fmaxf(mx1, __shfl_xor_sync(0xffffffffu, mx1, 1));
        mx1 = fmaxf(mx1, __shfl_xor_sync(0xffffffffu, mx1, 2));
        const float mn0 = fmaxf(m0, mx0), mn1 = fmaxf(m1, mx1);
        const float al0 = __expf(m0 - mn0), al1 = __expf(m1 - mn1);
#pragma unroll
        for (int j = 0; j < 8; j++) {
            o[j][0] *= al0; o[j][1] *= al0;
            o[j][2] *= al1; o[j][3] *= al1;
        }
        float sum0 = 0.f, sum1 = 0.f;
#pragma unroll
        for (int j = 0; j < 8; j++) {
            s[j][0] = __expf(s[j][0] - mn0);
            s[j][1] = __expf(s[j][1] - mn0);
            s[j][2] = __expf(s[j][2] - mn1);
            s[j][3] = __expf(s[j][3] - mn1);
            sum0 += s[j][0] + s[j][1];
            sum1 += s[j][2] + s[j][3];
        }
        sum0 += __shfl_xor_sync(0xffffffffu, sum0, 1);
        sum0 += __shfl_xor_sync(0xffffffffu, sum0, 2);
        sum1 += __shfl_xor_sync(0xffffffffu, sum1, 1);
        sum1 += __shfl_xor_sync(0xffffffffu, sum1, 2);
        l0 = l0 * al0 + sum0;
        l1 = l1 * al1 + sum1;
        m0 = mn0; m1 = mn1;

#pragma unroll
        for (int kk = 0; kk < 4; kk++) {
            uint32_t aph[4], apl[4];
            pack_split(s[2 * kk][0],     s[2 * kk][1],     aph[0], apl[0]);
            pack_split(s[2 * kk][2],     s[2 * kk][3],     aph[1], apl[1]);
            pack_split(s[2 * kk + 1][0], s[2 * kk + 1][1], aph[2], apl[2]);
            pack_split(s[2 * kk + 1][2], s[2 * kk + 1][3], aph[3], apl[3]);
            const uint32_t vroff = (uint32_t)((kk * 16 + v_r) * 128);
#pragma unroll
            for (int jn = 0; jn < 4; jn++) {
                const uint32_t vcb = ((uint32_t)(jn * 32) + v_cbb) ^ v_xor;
                uint32_t vh[4], vl[4];
                ldsm4t(st + 16384 + vroff + vcb, vh);
                ldsm4t(st + 24576 + vroff + vcb, vl);
                mma16816(o[2 * jn],     aph, vh[0], vh[1]);
                mma16816(o[2 * jn + 1], aph, vh[2], vh[3]);
                mma16816(o[2 * jn],     aph, vl[0], vl[1]);
                mma16816(o[2 * jn + 1], aph, vl[2], vl[3]);
                mma16816(o[2 * jn],     apl, vh[0], vh[1]);
                mma16816(o[2 * jn + 1], apl, vh[2], vh[3]);
            }
        }
        __syncthreads();
    }

    const int gr  = lane >> 2;
    const int cc2 = (lane & 3) * 2;
    const float inv0 = 1.f / l0, inv1 = 1.f / l1;
    const size_t r0 = rowbase + (size_t)(qt * 128 + wm + gr);
#pragma unroll
    for (int j = 0; j < 8; j++) {
        const int col = hcol + j * 8 + cc2;
        *(float2*)&out[r0 * EMBED + col] =
            make_float2(o[j][0] * inv0, o[j][1] * inv0);
        *(float2*)&out[(r0 + 8) * EMBED + col] =
            make_float2(o[j][2] * inv1, o[j][3] * inv1);
    }
}

// ============================================================================
// Launch
// ============================================================================
extern "C" void kernel_launch(void* const* d_in, const int* in_sizes, int n_in,
                              void* d_out, int out_size) {
    const float* x     = (const float*)d_in[0];
    const float* W_qkv = (const float*)d_in[1];
    const float* b_qkv = (const float*)d_in[2];
    const float* W_out = (const float*)d_in[3];
    const float* b_out = (const float*)d_in[4];
    float* out = (float*)d_out;

    float* attn_ptr;
    cudaGetSymbolAddress((void**)&attn_ptr, g_attn);
    __nv_bfloat16 *qkvh, *qkvl, *wq_hi, *wq_lo, *wo_hi, *wo_lo;
    cudaGetSymbolAddress((void**)&qkvh, g_qkvh);
    cudaGetSymbolAddress((void**)&qkvl, g_qkvl);
    cudaGetSymbolAddress((void**)&wq_hi, g_wq_hi);
    cudaGetSymbolAddress((void**)&wq_lo, g_wq_lo);
    cudaGetSymbolAddress((void**)&wo_hi, g_wo_hi);
    cudaGetSymbolAddress((void**)&wo_lo, g_wo_lo);

    cudaFuncSetAttribute(tc_gemm_bias, cudaFuncAttributeMaxDynamicSharedMemorySize, SM_GEMM_TOTAL);
    cudaFuncSetAttribute(attn_mma_kernel, cudaFuncAttributeMaxDynamicSharedMemorySize, ATT_SMEM);

    // 0) weight transpose + bf16 split
    wtrans_split_kernel<<<dim3(E3 / 32, EMBED / 32), 256>>>(W_qkv, wq_hi, wq_lo, EMBED, E3);
    wtrans_split_kernel<<<dim3(EMBED / 32, EMBED / 32), 256>>>(W_out, wo_hi, wo_lo, EMBED, EMBED);

    // 1) QKV projection (fp32 x input) -> pre-split bf16, Q pre-scaled by 0.125
    tc_gemm_bias<<<dim3(E3 / BN, M_TOTAL / BM), 128, SM_GEMM_TOTAL>>>(
        x, wq_hi, wq_lo, b_qkv, nullptr, qkvh, qkvl, M_TOTAL, E3, EMBED, EMBED);

    // 2) Attention (2 CTAs/SM) -> fp32
    dim3 g2(S_LEN / 128, HEADS, BATCH);
    attn_mma_kernel<<<g2, 256, ATT_SMEM>>>(qkvh, qkvl, attn_ptr);

    // 3) Output projection (fp32 attn input) -> fp32 final output
    tc_gemm_bias<<<dim3(EMBED / BN, M_TOTAL / BM), 128, SM_GEMM_TOTAL>>>(
        attn_ptr, wo_hi, wo_lo, b_out, out, nullptr, nullptr, M_TOTAL, EMBED, EMBED, 0);
}

// round 13
// speedup vs baseline: 1.0791x; 1.0791x over previous
#include <cuda_runtime.h>
#include <cuda_bf16.h>
#include <cstdint>

// ============================================================================
// Problem constants
// ============================================================================
#define S_LEN   2048
#define EMBED   1024
#define E3      3072
#define HEADS   16
#define HDIM    64
#define BATCH   4
#define M_TOTAL (BATCH * S_LEN) /* 8192 */

// Scratch (allocation-free contract)
__device__ __align__(16) __nv_bfloat16 g_xh[(size_t)M_TOTAL * EMBED];
__device__ __align__(16) __nv_bfloat16 g_xl[(size_t)M_TOTAL * EMBED];
__device__ __align__(16) __nv_bfloat16 g_qkvh[(size_t)M_TOTAL * E3];
__device__ __align__(16) __nv_bfloat16 g_qkvl[(size_t)M_TOTAL * E3];
__device__ __align__(16) __nv_bfloat16 g_attnh[(size_t)M_TOTAL * EMBED];
__device__ __align__(16) __nv_bfloat16 g_attnl[(size_t)M_TOTAL * EMBED];
__device__ __align__(16) __nv_bfloat16 g_wq_hi[(size_t)E3 * EMBED];
__device__ __align__(16) __nv_bfloat16 g_wq_lo[(size_t)E3 * EMBED];
__device__ __align__(16) __nv_bfloat16 g_wo_hi[(size_t)EMBED * EMBED];
__device__ __align__(16) __nv_bfloat16 g_wo_lo[(size_t)EMBED * EMBED];

// ============================================================================
// Helpers
// ============================================================================
__device__ __forceinline__ uint32_t smem_to_u32(const void* smem_ptr) {
    uint32_t addr;
    asm("{ .reg .u64 tmp; cvta.to.shared.u64 tmp, %1; cvt.u32.u64 %0, tmp; }"
        : "=r"(addr) : "l"(smem_ptr));
    return addr;
}

__device__ __forceinline__ void ldsm4(uint32_t addr, uint32_t r[4]) {
    asm volatile("ldmatrix.sync.aligned.m8n8.x4.shared.b16 {%0,%1,%2,%3}, [%4];"
                 : "=r"(r[0]), "=r"(r[1]), "=r"(r[2]), "=r"(r[3]) : "r"(addr));
}

__device__ __forceinline__ void ldsm4t(uint32_t addr, uint32_t r[4]) {
    asm volatile("ldmatrix.sync.aligned.m8n8.x4.trans.shared.b16 {%0,%1,%2,%3}, [%4];"
                 : "=r"(r[0]), "=r"(r[1]), "=r"(r[2]), "=r"(r[3]) : "r"(addr));
}

__device__ __forceinline__ void mma16816(float c[4], const uint32_t a[4],
                                         uint32_t b0, uint32_t b1) {
    asm volatile(
        "mma.sync.aligned.m16n8k16.row.col.f32.bf16.bf16.f32 "
        "{%0,%1,%2,%3}, {%4,%5,%6,%7}, {%8,%9}, {%0,%1,%2,%3};"
        : "+f"(c[0]), "+f"(c[1]), "+f"(c[2]), "+f"(c[3])
        : "r"(a[0]), "r"(a[1]), "r"(a[2]), "r"(a[3]), "r"(b0), "r"(b1));
}

__device__ __forceinline__ void cp_async16(uint32_t saddr, const void* gptr) {
    asm volatile("cp.async.cg.shared.global [%0], [%1], 16;"
                 :: "r"(saddr), "l"(gptr) : "memory");
}
#define CP_COMMIT() asm volatile("cp.async.commit_group;" ::: "memory")
#define CP_WAIT(n)  asm volatile("cp.async.wait_group %0;" :: "n"(n) : "memory")

__device__ __forceinline__ void split_bf16(float v, __nv_bfloat16& h, __nv_bfloat16& l) {
    h = __float2bfloat16(v);
    l = __float2bfloat16(v - __bfloat162float(h));
}

// pack (x,y) -> bf16x2 hi-word, residual pair -> lo-word
__device__ __forceinline__ void pack_split(float x, float y, uint32_t& hp, uint32_t& lp) {
    asm("cvt.rn.bf16x2.f32 %0, %1, %2;" : "=r"(hp) : "f"(y), "f"(x));
    const float hx = __uint_as_float(hp << 16);
    const float hy = __uint_as_float(hp & 0xffff0000u);
    const float rx = x - hx, ry = y - hy;
    asm("cvt.rn.bf16x2.f32 %0, %1, %2;" : "=r"(lp) : "f"(ry), "f"(rx));
}

// ============================================================================
// Prep 1: transpose W[K,N] -> Wt[N,K], split fp32 into bf16 hi + lo
// ============================================================================
__global__ __launch_bounds__(256)
void wtrans_split_kernel(const float* __restrict__ W, __nv_bfloat16* __restrict__ Th,
                         __nv_bfloat16* __restrict__ Tl, int K, int N) {
    __shared__ float t[32][33];
    const int n0 = blockIdx.x * 32, k0 = blockIdx.y * 32;
    const int tid = threadIdx.x;
    const int c = tid & 31, r = tid >> 5;
#pragma unroll
    for (int i = 0; i < 4; i++)
        t[r + i * 8][c] = W[(size_t)(k0 + r + i * 8) * N + n0 + c];
    __syncthreads();
    const int n  = tid >> 3;
    const int kq = (tid & 7) * 4;
    __nv_bfloat16 h[4], l[4];
#pragma unroll
    for (int j = 0; j < 4; j++) split_bf16(t[kq + j][n], h[j], l[j]);
    const size_t o = (size_t)(n0 + n) * K + k0 + kq;
    *(__nv_bfloat162*)&Th[o]     = __halves2bfloat162(h[0], h[1]);
    *(__nv_bfloat162*)&Th[o + 2] = __halves2bfloat162(h[2], h[3]);
    *(__nv_bfloat162*)&Tl[o]     = __halves2bfloat162(l[0], l[1]);
    *(__nv_bfloat162*)&Tl[o + 2] = __halves2bfloat162(l[2], l[3]);
}

// ============================================================================
// Prep 2: elementwise fp32 -> bf16 hi/lo split (for x)
// ============================================================================
__global__ __launch_bounds__(256)
void fsplit_kernel(const float* __restrict__ X, __nv_bfloat16* __restrict__ Xh,
                   __nv_bfloat16* __restrict__ Xl) {
    const size_t idx = (size_t)blockIdx.x * 256 + threadIdx.x;
    const float4 v = ((const float4*)X)[idx];
    uint32_t h0, l0, h1, l1;
    pack_split(v.x, v.y, h0, l0);
    pack_split(v.z, v.w, h1, l1);
    ((uint2*)Xh)[idx] = make_uint2(h0, h1);
    ((uint2*)Xl)[idx] = make_uint2(l0, l1);
}

// ============================================================================
// HMMA GEMM, 2-CTA/SM, measured-best 64x32 warp tile preserved:
// CTA = 128 threads (4 warps, 1x4 in N), tile 64(M) x 128(N), BK=64.
// Pre-split bf16 A, cp.async 2-stage producer. Stage 48KB, smem 96KB ->
// 2 CTAs/SM with NO register clamp (128 thr -> 255-reg budget).
// ============================================================================
#define BM 64
#define BN 128
#define BK 64
#define A_TILE 8192             /* 64 rows x 128B, per h/l */
#define B_TILE 16384            /* 128 rows x 128B, per h/l */
#define OFF_AH 0
#define OFF_AL A_TILE
#define OFF_BH (2 * A_TILE)
#define OFF_BL (2 * A_TILE + B_TILE)
#define STAGE_SZ  (2 * A_TILE + 2 * B_TILE)   /* 49152 */
#define SM_GEMM_TOTAL (2 * STAGE_SZ)          /* 98304 */

__global__ __launch_bounds__(128, 2)
void tc_gemm_bias(const __nv_bfloat16* __restrict__ Ah, const __nv_bfloat16* __restrict__ Al,
                  const __nv_bfloat16* __restrict__ Bth, const __nv_bfloat16* __restrict__ Btl,
                  const float* __restrict__ bias,
                  float* __restrict__ Cf, __nv_bfloat16* __restrict__ Ch,
                  __nv_bfloat16* __restrict__ Cl,
                  int M, int N, int K, int scale_cols) {
    extern __shared__ char smem[];
    __shared__ float sbias[BN];
    const uint32_t sb = smem_to_u32(smem);
    const int tid  = threadIdx.x;
    const int wid  = tid >> 5;
    const int lane = tid & 31;
    const int row0 = blockIdx.y * BM;
    const int col0 = blockIdx.x * BN;
    const int nchunks = K / BK;

    if (tid < BN) sbias[tid] = bias[col0 + tid];

    // ---- producer: thread owns 1 A row-slot (hi or lo) + Bh row + Bl row ----
    const __nv_bfloat16* pA = (tid < 64) ? (Ah + (size_t)(row0 + tid) * K)
                                         : (Al + (size_t)(row0 + (tid - 64)) * K);
    const uint32_t pA_base = (uint32_t)((tid < 64 ? OFF_AH : OFF_AL) + (tid & 63) * 128);
    const uint32_t pA_sw   = ((uint32_t)tid & 7) << 4;
    const __nv_bfloat16* pBh = Bth + (size_t)(col0 + tid) * K;
    const __nv_bfloat16* pBl = Btl + (size_t)(col0 + tid) * K;
    const uint32_t pBh_base = (uint32_t)(OFF_BH + tid * 128);
    const uint32_t pBl_base = (uint32_t)(OFF_BL + tid * 128);
    const uint32_t pB_sw    = ((uint32_t)tid & 7) << 4;

    auto issue = [&](int c) {
        const uint32_t st = sb + (uint32_t)(c & 1) * STAGE_SZ;
        const int k0 = c * BK;
#pragma unroll
        for (int i = 0; i < 8; i++) {
            const uint32_t bc = (uint32_t)(i * 16);
            cp_async16(st + pA_base  + (bc ^ pA_sw), pA  + k0 + (bc >> 1));
            cp_async16(st + pBh_base + (bc ^ pB_sw), pBh + k0 + (bc >> 1));
            cp_async16(st + pBl_base + (bc ^ pB_sw), pBl + k0 + (bc >> 1));
        }
        CP_COMMIT();
    };

    // ---- consumer: 1x4 warp grid, warp tile 64x32 (r4-identical inner) ----
    const int wm = 0;
    const int wn = wid * 32;
    const int a_r    = lane & 15;
    const int a_half = lane >> 4;
    const int b_nr   = (lane & 7) | ((lane >> 4) << 3);
    const int b_kh   = (lane >> 3) & 1;

    uint32_t a_rowoff[4], a_xor[4], b_rowoff[2], b_xor[2];
#pragma unroll
    for (int i = 0; i < 4; i++) {
        const int r = wm + i * 16 + a_r;
        a_rowoff[i] = (uint32_t)(r * 128);
        a_xor[i]    = (uint32_t)((r & 7) << 4);
    }
#pragma unroll
    for (int jp = 0; jp < 2; jp++) {
        const int r = wn + jp * 16 + b_nr;
        b_rowoff[jp] = (uint32_t)(r * 128);
        b_xor[jp]    = (uint32_t)((r & 7) << 4);
    }
    const uint32_t a_kbb = (uint32_t)(a_half * 16);
    const uint32_t b_kbb = (uint32_t)(b_kh * 16);

    float acc[4][4][4];
#pragma unroll
    for (int i = 0; i < 4; i++)
#pragma unroll
        for (int j = 0; j < 4; j++)
#pragma unroll
            for (int q = 0; q < 4; q++) acc[i][j][q] = 0.f;

    issue(0);
    issue(1);

    for (int c = 0; c < nchunks; c++) {
        if (c + 1 < nchunks) { CP_WAIT(1); } else { CP_WAIT(0); }
        __syncthreads();

        const uint32_t st = sb + (uint32_t)(c & 1) * STAGE_SZ;
#pragma unroll
        for (int ks = 0; ks < 4; ks++) {
            const uint32_t kbA = (uint32_t)(ks * 32) + a_kbb;
            const uint32_t kbB = (uint32_t)(ks * 32) + b_kbb;
            uint32_t ah[4][4], al[4][4], bh[2][4], bl[2][4];
#pragma unroll
            for (int i = 0; i < 4; i++) {
                ldsm4(st + OFF_AH + a_rowoff[i] + (kbA ^ a_xor[i]), ah[i]);
                ldsm4(st + OFF_AL + a_rowoff[i] + (kbA ^ a_xor[i]), al[i]);
            }
#pragma unroll
            for (int jp = 0; jp < 2; jp++) {
                ldsm4(st + OFF_BH + b_rowoff[jp] + (kbB ^ b_xor[jp]), bh[jp]);
                ldsm4(st + OFF_BL + b_rowoff[jp] + (kbB ^ b_xor[jp]), bl[jp]);
            }
#pragma unroll
            for (int i = 0; i < 4; i++)
#pragma unroll
                for (int j = 0; j < 4; j++)
                    mma16816(acc[i][j], ah[i], bh[j >> 1][(j & 1) * 2], bh[j >> 1][(j & 1) * 2 + 1]);
#pragma unroll
            for (int i = 0; i < 4; i++)
#pragma unroll
                for (int j = 0; j < 4; j++)
                    mma16816(acc[i][j], ah[i], bl[j >> 1][(j & 1) * 2], bl[j >> 1][(j & 1) * 2 + 1]);
#pragma unroll
            for (int i = 0; i < 4; i++)
#pragma unroll
                for (int j = 0; j < 4; j++)
                    mma16816(acc[i][j], al[i], bh[j >> 1][(j & 1) * 2], bh[j >> 1][(j & 1) * 2 + 1]);
        }
        __syncthreads();
        if (c + 2 < nchunks) issue(c + 2);
    }

    // ---- epilogue ----
    const int cr  = lane >> 2;
    const int cc2 = (lane & 3) * 2;
#pragma unroll
    for (int i = 0; i < 4; i++) {
#pragma unroll
        for (int j = 0; j < 4; j++) {
            const int col  = wn + j * 8 + cc2;
            const int gcol = col0 + col;
            const int r0 = row0 + wm + i * 16 + cr;
            float v0 = acc[i][j][0] + sbias[col];
            float v1 = acc[i][j][1] + sbias[col + 1];
            float v2 = acc[i][j][2] + sbias[col];
            float v3 = acc[i][j][3] + sbias[col + 1];
            if (gcol < scale_cols) { v0 *= 0.125f; v1 *= 0.125f; v2 *= 0.125f; v3 *= 0.125f; }
            if (Ch) {
                uint32_t hp, lp;
                pack_split(v0, v1, hp, lp);
                *(uint32_t*)&Ch[(size_t)r0 * N + gcol] = hp;
                *(uint32_t*)&Cl[(size_t)r0 * N + gcol] = lp;
                pack_split(v2, v3, hp, lp);
                *(uint32_t*)&Ch[(size_t)(r0 + 8) * N + gcol] = hp;
                *(uint32_t*)&Cl[(size_t)(r0 + 8) * N + gcol] = lp;
            } else {
                *(float2*)&Cf[(size_t)r0 * N + gcol]       = make_float2(v0, v1);
                *(float2*)&Cf[(size_t)(r0 + 8) * N + gcol] = make_float2(v2, v3);
            }
        }
    }
}

// ============================================================================
// HMMA flash attention (round-10/11 winner body, split bf16 output).
// CTA = 128 q-rows x (head, batch), 8 warps, K/V tiles 64 rows,
// double-buffered, 2 CTAs/SM.
// ============================================================================
#define ATT_STAGE 32768
#define ATT_SMEM  (32768 + 2 * ATT_STAGE)  /* 98304 */
#define KT_ROWS   64

__global__ __launch_bounds__(256, 2)
void attn_mma_kernel(const __nv_bfloat16* __restrict__ QKVh,
                     const __nv_bfloat16* __restrict__ QKVl,
                     __nv_bfloat16* __restrict__ Oh,
                     __nv_bfloat16* __restrict__ Ol) {
    extern __shared__ char smem[];
    const uint32_t sb = smem_to_u32(smem);
    const int tid = threadIdx.x, wid = tid >> 5, lane = tid & 31;
    const int qt = blockIdx.x, h = blockIdx.y, b = blockIdx.z;
    const size_t rowbase = (size_t)b * S_LEN;
    const int hcol = h * HDIM;

    const uint32_t sQH = sb, sQL = sb + 16384;

    {
        const int p_r  = tid >> 1;
        const int p_cb = (tid & 1) * 64;
        const size_t grow = (rowbase + qt * 128 + p_r) * E3 + hcol;
#pragma unroll
        for (int i = 0; i < 4; i++) {
            const uint32_t bc  = (uint32_t)(p_cb + i * 16);
            const uint32_t off = (uint32_t)(p_r * 128) + (bc ^ (((uint32_t)p_r & 7) << 4));
            cp_async16(sQH + off, QKVh + grow + (bc >> 1));
            cp_async16(sQL + off, QKVl + grow + (bc >> 1));
        }
    }
    const int q_r  = tid >> 2;
    const int q_cb = (tid & 3) * 32;
    auto issue_kv = [&](int kt) {
        const uint32_t st = sb + 32768 + (uint32_t)(kt & 1) * ATT_STAGE;
        const size_t growK = (rowbase + kt * KT_ROWS + q_r) * E3 + (EMBED + hcol);
        const size_t growV = growK + EMBED;
#pragma unroll
        for (int i = 0; i < 2; i++) {
            const uint32_t bc  = (uint32_t)(q_cb + i * 16);
            const uint32_t off = (uint32_t)(q_r * 128) + (bc ^ (((uint32_t)q_r & 7) << 4));
            cp_async16(st + off,         QKVh + growK + (bc >> 1));
            cp_async16(st + 8192 + off,  QKVl + growK + (bc >> 1));
            cp_async16(st + 16384 + off, QKVh + growV + (bc >> 1));
            cp_async16(st + 24576 + off, QKVl + growV + (bc >> 1));
        }
    };
    issue_kv(0);
    CP_COMMIT();

    const int wm = wid * 16;
    const int a_row = wm + (lane & 15);
    const uint32_t a_rowoff = (uint32_t)(a_row * 128);
    const uint32_t a_xor    = ((uint32_t)a_row & 7) << 4;
    const uint32_t a_kbb    = (uint32_t)((lane >> 4) * 16);
    const int b_nr = (lane & 7) | ((lane >> 4) << 3);
    const uint32_t b_kbb = (uint32_t)(((lane >> 3) & 1) * 16);
    const uint32_t b_xor = ((uint32_t)lane & 7) << 4;
    const int v_r = ((lane >> 3) & 1) * 8 + (lane & 7);
    const uint32_t v_cbb = (uint32_t)((lane >> 4) * 16);
    const uint32_t v_xor = ((uint32_t)lane & 7) << 4;

    float m0 = -1e30f, m1 = -1e30f, l0 = 0.f, l1 = 0.f;
    float o[8][4];
#pragma unroll
    for (int j = 0; j < 8; j++)
#pragma unroll
        for (int q = 0; q < 4; q++) o[j][q] = 0.f;

    for (int kt = 0; kt < S_LEN / KT_ROWS; kt++) {
        const uint32_t st = sb + 32768 + (uint32_t)(kt & 1) * ATT_STAGE;
        if (kt + 1 < S_LEN / KT_ROWS) {
            issue_kv(kt + 1);
            CP_COMMIT();
            asm volatile("cp.async.wait_group 1;" ::: "memory");
        } else {
            asm volatile("cp.async.wait_group 0;" ::: "memory");
        }
        __syncthreads();

        float s[8][4];
#pragma unroll
        for (int j = 0; j < 8; j++)
#pragma unroll
            for (int q = 0; q < 4; q++) s[j][q] = 0.f;

#pragma unroll
        for (int ks = 0; ks < 4; ks++) {
            const uint32_t akb = (uint32_t)(ks * 32) + a_kbb;
            uint32_t qh[4], ql[4];
            ldsm4(sQH + a_rowoff + (akb ^ a_xor), qh);
            ldsm4(sQL + a_rowoff + (akb ^ a_xor), ql);
            const uint32_t kcb = ((uint32_t)(ks * 32) + b_kbb) ^ b_xor;
#pragma unroll
            for (int jp = 0; jp < 4; jp++) {
                const uint32_t roff = (uint32_t)((jp * 16 + b_nr) * 128);
                uint32_t kh[4], kl[4];
                ldsm4(st + roff + kcb, kh);
                ldsm4(st + 8192 + roff + kcb, kl);
                mma16816(s[2 * jp],     qh, kh[0], kh[1]);
                mma16816(s[2 * jp + 1], qh, kh[2], kh[3]);
                mma16816(s[2 * jp],     qh, kl[0], kl[1]);
                mma16816(s[2 * jp + 1], qh, kl[2], kl[3]);
                mma16816(s[2 * jp],     ql, kh[0], kh[1]);
                mma16816(s[2 * jp + 1], ql, kh[2], kh[3]);
            }
        }

        float mx0 = -1e30f, mx1 = -1e30f;
#pragma unroll
        for (int j = 0; j < 8; j++) {
            mx0 = fmaxf(mx0, fmaxf(s[j][0], s[j][1]));
            mx1 = fmaxf(mx1, fmaxf(s[j][2], s[j][3]));
        }
        mx0 = fmaxf(mx0, __shfl_xor_sync(0xffffffffu, mx0, 1));
        mx0 = fmaxf(mx0, __shfl_xor_sync(0xffffffffu, mx0, 2));
        mx1 = fmaxf(mx1, __shfl_xor_sync(0xffffffffu, mx1, 1));
        mx1 = fmaxf(mx1, __shfl_xor_sync(0xffffffffu, mx1, 2));
        const float mn0 = fmaxf(m0, mx0), mn1 = fmaxf(m1, mx1);
        const float al0 = __expf(m0 - mn0), al1 = __expf(m1 - mn1);
#pragma unroll
        for (int j = 0; j < 8; j++) {
            o[j][0] *= al0; o[j][1] *= al0;
            o[j][2] *= al1; o[j][3] *= al1;
        }
        float sum0 = 0.f, sum1 = 0.f;
#pragma unroll
        for (int j = 0; j < 8; j++) {
            s[j][0] = __expf(s[j][0] - mn0);
            s[j][1] = __expf(s[j][1] - mn0);
            s[j][2] = __expf(s[j][2] - mn1);
            s[j][3] = __expf(s[j][3] - mn1);
            sum0 += s[j][0] + s[j][1];
            sum1 += s[j][2] + s[j][3];
        }
        sum0 += __shfl_xor_sync(0xffffffffu, sum0, 1);
        sum0 += __shfl_xor_sync(0xffffffffu, sum0, 2);
        sum1 += __shfl_xor_sync(0xffffffffu, sum1, 1);
        sum1 += __shfl_xor_sync(0xffffffffu, sum1, 2);
        l0 = l0 * al0 + sum0;
        l1 = l1 * al1 + sum1;
        m0 = mn0; m1 = mn1;

#pragma unroll
        for (int kk = 0; kk < 4; kk++) {
            uint32_t aph[4], apl[4];
            pack_split(s[2 * kk][0],     s[2 * kk][1],     aph[0], apl[0]);
            pack_split(s[2 * kk][2],     s[2 * kk][3],     aph[1], apl[1]);
            pack_split(s[2 * kk + 1][0], s[2 * kk + 1][1], aph[2], apl[2]);
            pack_split(s[2 * kk + 1][2], s[2 * kk + 1][3], aph[3], apl[3]);
            const uint32_t vroff = (uint32_t)((kk * 16 + v_r) * 128);
#pragma unroll
            for (int jn = 0; jn < 4; jn++) {
                const uint32_t vcb = ((uint32_t)(jn * 32) + v_cbb) ^ v_xor;
                uint32_t vh[4], vl[4];
                ldsm4t(st + 16384 + vroff + vcb, vh);
                ldsm4t(st + 24576 + vroff + vcb, vl);
                mma16816(o[2 * jn],     aph, vh[0], vh[1]);
                mma16816(o[2 * jn + 1], aph, vh[2], vh[3]);
                mma16816(o[2 * jn],     aph, vl[0], vl[1]);
                mma16816(o[2 * jn + 1], aph, vl[2], vl[3]);
                mma16816(o[2 * jn],     apl, vh[0], vh[1]);
                mma16816(o[2 * jn + 1], apl, vh[2], vh[3]);
            }
        }
        __syncthreads();
    }

    // === epilogue: normalize, pre-split bf16, write ===
    const int gr  = lane >> 2;
    const int cc2 = (lane & 3) * 2;
    const float inv0 = 1.f / l0, inv1 = 1.f / l1;
    const size_t r0 = rowbase + (size_t)(qt * 128 + wm + gr);
#pragma unroll
    for (int j = 0; j < 8; j++) {
        const int col = hcol + j * 8 + cc2;
        uint32_t hp, lp;
        pack_split(o[j][0] * inv0, o[j][1] * inv0, hp, lp);
        *(uint32_t*)&Oh[r0 * EMBED + col] = hp;
        *(uint32_t*)&Ol[r0 * EMBED + col] = lp;
        pack_split(o[j][2] * inv1, o[j][3] * inv1, hp, lp);
        *(uint32_t*)&Oh[(r0 + 8) * EMBED + col] = hp;
        *(uint32_t*)&Ol[(r0 + 8) * EMBED + col] = lp;
    }
}

// ============================================================================
// Launch
// ============================================================================
extern "C" void kernel_launch(void* const* d_in, const int* in_sizes, int n_in,
                              void* d_out, int out_size) {
    const float* x     = (const float*)d_in[0];
    const float* W_qkv = (const float*)d_in[1];
    const float* b_qkv = (const float*)d_in[2];
    const float* W_out = (const float*)d_in[3];
    const float* b_out = (const float*)d_in[4];
    float* out = (float*)d_out;

    __nv_bfloat16 *xh, *xl, *qkvh, *qkvl, *attnh, *attnl;
    __nv_bfloat16 *wq_hi, *wq_lo, *wo_hi, *wo_lo;
    cudaGetSymbolAddress((void**)&xh, g_xh);
    cudaGetSymbolAddress((void**)&xl, g_xl);
    cudaGetSymbolAddress((void**)&qkvh, g_qkvh);
    cudaGetSymbolAddress((void**)&qkvl, g_qkvl);
    cudaGetSymbolAddress((void**)&attnh, g_attnh);
    cudaGetSymbolAddress((void**)&attnl, g_attnl);
    cudaGetSymbolAddress((void**)&wq_hi, g_wq_hi);
    cudaGetSymbolAddress((void**)&wq_lo, g_wq_lo);
    cudaGetSymbolAddress((void**)&wo_hi, g_wo_hi);
    cudaGetSymbolAddress((void**)&wo_lo, g_wo_lo);

    cudaFuncSetAttribute(tc_gemm_bias, cudaFuncAttributeMaxDynamicSharedMemorySize, SM_GEMM_TOTAL);
    cudaFuncSetAttribute(attn_mma_kernel, cudaFuncAttributeMaxDynamicSharedMemorySize, ATT_SMEM);

    // 0) prep: weight transpose+split, x split
    wtrans_split_kernel<<<dim3(E3 / 32, EMBED / 32), 256>>>(W_qkv, wq_hi, wq_lo, EMBED, E3);
    wtrans_split_kernel<<<dim3(EMBED / 32, EMBED / 32), 256>>>(W_out, wo_hi, wo_lo, EMBED, EMBED);
    fsplit_kernel<<<(M_TOTAL * EMBED / 4) / 256, 256>>>(x, xh, xl);

    // 1) QKV projection -> pre-split bf16, Q pre-scaled by 0.125
    tc_gemm_bias<<<dim3(E3 / BN, M_TOTAL / BM), 128, SM_GEMM_TOTAL>>>(
        xh, xl, wq_hi, wq_lo, b_qkv, nullptr, qkvh, qkvl, M_TOTAL, E3, EMBED, EMBED);

    // 2) Attention (2 CTAs/SM) -> pre-split bf16
    dim3 g2(S_LEN / 128, HEADS, BATCH);
    attn_mma_kernel<<<g2, 256, ATT_SMEM>>>(qkvh, qkvl, attnh, attnl);

    // 3) Output projection -> fp32 final output
    tc_gemm_bias<<<dim3(EMBED / BN, M_TOTAL / BM), 128, SM_GEMM_TOTAL>>>(
        attnh, attnl, wo_hi, wo_lo, b_out, out, nullptr, nullptr, M_TOTAL, EMBED, EMBED, 0);
}

// round 14
// speedup vs baseline: 1.4362x; 1.3310x over previous
#include <cuda_runtime.h>
#include <cuda_bf16.h>
#include <cstdint>

// ============================================================================
// Problem constants
// ============================================================================
#define S_LEN   2048
#define EMBED   1024
#define E3      3072
#define HEADS   16
#define HDIM    64
#define BATCH   4
#define M_TOTAL (BATCH * S_LEN) /* 8192 */

// Scratch (allocation-free contract)
__device__ __align__(16) __nv_bfloat16 g_qkvh[(size_t)M_TOTAL * E3]; // ~50MB
__device__ __align__(16) __nv_bfloat16 g_qkvl[(size_t)M_TOTAL * E3]; // ~50MB
__device__ float g_attn[(size_t)M_TOTAL * EMBED];                    // ~33.6 MB
__device__ __align__(16) __nv_bfloat16 g_wq_hi[(size_t)E3 * EMBED];
__device__ __align__(16) __nv_bfloat16 g_wq_lo[(size_t)E3 * EMBED];
__device__ __align__(16) __nv_bfloat16 g_wo_hi[(size_t)EMBED * EMBED];
__device__ __align__(16) __nv_bfloat16 g_wo_lo[(size_t)EMBED * EMBED];

// ============================================================================
// Helpers
// ============================================================================
__device__ __forceinline__ uint32_t smem_to_u32(const void* smem_ptr) {
    uint32_t addr;
    asm("{ .reg .u64 tmp; cvta.to.shared.u64 tmp, %1; cvt.u32.u64 %0, tmp; }"
        : "=r"(addr) : "l"(smem_ptr));
    return addr;
}

#define SMEM_SWIZZLE_128B(byte_offset) \
    ((byte_offset) ^ (((byte_offset) >> 3) & 0x70))

__device__ __forceinline__ void ldsm4(uint32_t addr, uint32_t r[4]) {
    asm volatile("ldmatrix.sync.aligned.m8n8.x4.shared.b16 {%0,%1,%2,%3}, [%4];"
                 : "=r"(r[0]), "=r"(r[1]), "=r"(r[2]), "=r"(r[3]) : "r"(addr));
}

__device__ __forceinline__ void ldsm4t(uint32_t addr, uint32_t r[4]) {
    asm volatile("ldmatrix.sync.aligned.m8n8.x4.trans.shared.b16 {%0,%1,%2,%3}, [%4];"
                 : "=r"(r[0]), "=r"(r[1]), "=r"(r[2]), "=r"(r[3]) : "r"(addr));
}

__device__ __forceinline__ void mma16816(float c[4], const uint32_t a[4],
                                         uint32_t b0, uint32_t b1) {
    asm volatile(
        "mma.sync.aligned.m16n8k16.row.col.f32.bf16.bf16.f32 "
        "{%0,%1,%2,%3}, {%4,%5,%6,%7}, {%8,%9}, {%0,%1,%2,%3};"
        : "+f"(c[0]), "+f"(c[1]), "+f"(c[2]), "+f"(c[3])
        : "r"(a[0]), "r"(a[1]), "r"(a[2]), "r"(a[3]), "r"(b0), "r"(b1));
}

__device__ __forceinline__ void cp_async16(uint32_t saddr, const void* gptr) {
    asm volatile("cp.async.cg.shared.global [%0], [%1], 16;"
                 :: "r"(saddr), "l"(gptr) : "memory");
}
#define CP_COMMIT() asm volatile("cp.async.commit_group;" ::: "memory")

__device__ __forceinline__ void split_bf16(float v, __nv_bfloat16& h, __nv_bfloat16& l) {
    h = __float2bfloat16(v);
    l = __float2bfloat16(v - __bfloat162float(h));
}

__device__ __forceinline__ uint32_t pack_bf16(__nv_bfloat16 a, __nv_bfloat16 b) {
    __nv_bfloat162 t = __halves2bfloat162(a, b);
    return *reinterpret_cast<uint32_t*>(&t);
}

// pack (x,y) -> bf16x2 hi-word, residual pair -> lo-word
__device__ __forceinline__ void pack_split(float x, float y, uint32_t& hp, uint32_t& lp) {
    asm("cvt.rn.bf16x2.f32 %0, %1, %2;" : "=r"(hp) : "f"(y), "f"(x));
    const float hx = __uint_as_float(hp << 16);
    const float hy = __uint_as_float(hp & 0xffff0000u);
    const float rx = x - hx, ry = y - hy;
    asm("cvt.rn.bf16x2.f32 %0, %1, %2;" : "=r"(lp) : "f"(ry), "f"(rx));
}

// ============================================================================
// Prep (fused): transpose W[K,N] -> Wt[N,K], split fp32 into bf16 hi + lo.
// blockIdx.z = 0 -> W_qkv (N=3072), 1 -> W_out (N=1024). K = 1024 for both.
// Out-of-range blocks (z=1, n0 >= 1024) return early.
// ============================================================================
__global__ __launch_bounds__(256)
void wtrans_split2_kernel(const float* __restrict__ W0, __nv_bfloat16* __restrict__ Th0,
                          __nv_bfloat16* __restrict__ Tl0,
                          const float* __restrict__ W1, __nv_bfloat16* __restrict__ Th1,
                          __nv_bfloat16* __restrict__ Tl1) {
    const int z = blockIdx.z;
    const int N = z ? EMBED : E3;
    const int n0 = blockIdx.x * 32, k0 = blockIdx.y * 32;
    if (n0 >= N) return;
    const float* W = z ? W1 : W0;
    __nv_bfloat16* Th = z ? Th1 : Th0;
    __nv_bfloat16* Tl = z ? Tl1 : Tl0;
    const int K = EMBED;

    __shared__ float t[32][33];
    const int tid = threadIdx.x;
    const int c = tid & 31, r = tid >> 5;
#pragma unroll
    for (int i = 0; i < 4; i++)
        t[r + i * 8][c] = W[(size_t)(k0 + r + i * 8) * N + n0 + c];
    __syncthreads();
    const int n  = tid >> 3;
    const int kq = (tid & 7) * 4;
    __nv_bfloat16 h[4], l[4];
#pragma unroll
    for (int j = 0; j < 4; j++) split_bf16(t[kq + j][n], h[j], l[j]);
    const size_t o = (size_t)(n0 + n) * K + k0 + kq;
    *(__nv_bfloat162*)&Th[o]     = __halves2bfloat162(h[0], h[1]);
    *(__nv_bfloat162*)&Th[o + 2] = __halves2bfloat162(h[2], h[3]);
    *(__nv_bfloat162*)&Tl[o]     = __halves2bfloat162(l[0], l[1]);
    *(__nv_bfloat162*)&Tl[o + 2] = __halves2bfloat162(l[2], l[3]);
}

// ============================================================================
// HMMA GEMM (round-4/10 measured best): C = A[M,K](fp32) @ Bt[N,K](bf16
// hi/lo) + bias. 3-term split, register gmem prefetch + in-kernel A split,
// double-buffered smem. CTA 128x128, BK=64, 8 warps, warp tile 64x32.
// Output fp32 (Cf) or pre-split bf16 (Ch/Cl); cols < scale_cols scaled 0.125.
// ============================================================================
#define BM 128
#define BN 128
#define BK 64
#define TILE_SZ   16384
#define STAGE_SZ  (4 * TILE_SZ)
#define SM_GEMM_TOTAL (2 * STAGE_SZ)

__global__ __launch_bounds__(256, 1)
void tc_gemm_bias(const float* __restrict__ A, const __nv_bfloat16* __restrict__ Bth,
                  const __nv_bfloat16* __restrict__ Btl, const float* __restrict__ bias,
                  float* __restrict__ Cf, __nv_bfloat16* __restrict__ Ch,
                  __nv_bfloat16* __restrict__ Cl,
                  int M, int N, int K, int scale_cols) {
    extern __shared__ char smem[];
    __shared__ float sbias[BN];
    const uint32_t sb = smem_to_u32(smem);
    const int tid  = threadIdx.x;
    const int wid  = tid >> 5;
    const int lane = tid & 31;
    const int row0 = blockIdx.y * BM;
    const int col0 = blockIdx.x * BN;
    const int nchunks = K / BK;

    if (tid < BN) sbias[tid] = bias[col0 + tid];

    const int a_kq = (tid & 15) * 4;
    const int a_m0 = tid >> 4;
    const int b_kg = (tid & 7) * 8;
    const int b_n0 = tid >> 3;

    uint32_t a_soff[8], b_soff[4];
#pragma unroll
    for (int i = 0; i < 8; i++) {
        const int m = a_m0 + i * 16;
        a_soff[i] = SMEM_SWIZZLE_128B((uint32_t)(m * 128 + a_kq * 2));
    }
#pragma unroll
    for (int i = 0; i < 4; i++) {
        const int n = b_n0 + i * 32;
        b_soff[i] = SMEM_SWIZZLE_128B((uint32_t)(n * 128 + b_kg * 2));
    }

    const int wm = (wid >> 2) * 64;
    const int wn = (wid & 3) * 32;
    const int a_r    = lane & 15;
    const int a_half = lane >> 4;
    const int b_nr   = (lane & 7) | ((lane >> 4) << 3);
    const int b_kh   = (lane >> 3) & 1;

    uint32_t a_rowoff[4], a_xor[4], b_rowoff[2], b_xor[2];
#pragma unroll
    for (int i = 0; i < 4; i++) {
        const int r = wm + i * 16 + a_r;
        a_rowoff[i] = (uint32_t)(r * 128);
        a_xor[i]    = (uint32_t)((r & 7) << 4);
    }
#pragma unroll
    for (int jp = 0; jp < 2; jp++) {
        const int r = wn + jp * 16 + b_nr;
        b_rowoff[jp] = (uint32_t)(r * 128);
        b_xor[jp]    = (uint32_t)((r & 7) << 4);
    }
    const uint32_t a_kbb = (uint32_t)(a_half * 16);
    const uint32_t b_kbb = (uint32_t)(b_kh * 16);

    float acc[4][4][4];
#pragma unroll
    for (int i = 0; i < 4; i++)
#pragma unroll
        for (int j = 0; j < 4; j++)
#pragma unroll
            for (int q = 0; q < 4; q++) acc[i][j][q] = 0.f;

    {
        const uint32_t st = sb;
#pragma unroll
        for (int i = 0; i < 8; i++) {
            const int m = a_m0 + i * 16;
            const float4 v = *(const float4*)&A[(size_t)(row0 + m) * K + a_kq];
            __nv_bfloat16 h0, h1, h2, h3, l0, l1, l2, l3;
            split_bf16(v.x, h0, l0); split_bf16(v.y, h1, l1);
            split_bf16(v.z, h2, l2); split_bf16(v.w, h3, l3);
            asm volatile("st.shared.v2.b32 [%0], {%1, %2};"
                :: "r"(st + a_soff[i]), "r"(pack_bf16(h0, h1)), "r"(pack_bf16(h2, h3)) : "memory");
            asm volatile("st.shared.v2.b32 [%0], {%1, %2};"
                :: "r"(st + TILE_SZ + a_soff[i]), "r"(pack_bf16(l0, l1)), "r"(pack_bf16(l2, l3)) : "memory");
        }
#pragma unroll
        for (int i = 0; i < 4; i++) {
            const int n = b_n0 + i * 32;
            const size_t g = (size_t)(col0 + n) * K + b_kg;
            const uint4 vh = *(const uint4*)&Bth[g];
            const uint4 vl = *(const uint4*)&Btl[g];
            asm volatile("st.shared.v4.b32 [%0], {%1, %2, %3, %4};"
                :: "r"(st + 2 * TILE_SZ + b_soff[i]), "r"(vh.x), "r"(vh.y), "r"(vh.z), "r"(vh.w) : "memory");
            asm volatile("st.shared.v4.b32 [%0], {%1, %2, %3, %4};"
                :: "r"(st + 3 * TILE_SZ + b_soff[i]), "r"(vl.x), "r"(vl.y), "r"(vl.z), "r"(vl.w) : "memory");
        }
    }
    __syncthreads();

    for (int c = 0; c < nchunks; c++) {
        const uint32_t st = sb + (uint32_t)(c & 1) * STAGE_SZ;

        float4 pa[8];
        uint4 pbh[4], pbl[4];
        const bool more = (c + 1 < nchunks);
        if (more) {
            const int k0n = (c + 1) * BK;
#pragma unroll
            for (int i = 0; i < 8; i++) {
                const int m = a_m0 + i * 16;
                pa[i] = *(const float4*)&A[(size_t)(row0 + m) * K + k0n + a_kq];
            }
#pragma unroll
            for (int i = 0; i < 4; i++) {
                const int n = b_n0 + i * 32;
                const size_t g = (size_t)(col0 + n) * K + k0n + b_kg;
                pbh[i] = *(const uint4*)&Bth[g];
                pbl[i] = *(const uint4*)&Btl[g];
            }
        }

        const uint32_t stAh = st, stAl = st + TILE_SZ;
        const uint32_t stBh = st + 2 * TILE_SZ, stBl = st + 3 * TILE_SZ;
#pragma unroll
        for (int ks = 0; ks < 4; ks++) {
            const uint32_t kbA = (uint32_t)(ks * 32) + a_kbb;
            const uint32_t kbB = (uint32_t)(ks * 32) + b_kbb;
            uint32_t ah[4][4], al[4][4], bh[2][4], bl[2][4];
#pragma unroll
            for (int i = 0; i < 4; i++) {
                ldsm4(stAh + a_rowoff[i] + (kbA ^ a_xor[i]), ah[i]);
                ldsm4(stAl + a_rowoff[i] + (kbA ^ a_xor[i]), al[i]);
            }
#pragma unroll
            for (int jp = 0; jp < 2; jp++) {
                ldsm4(stBh + b_rowoff[jp] + (kbB ^ b_xor[jp]), bh[jp]);
                ldsm4(stBl + b_rowoff[jp] + (kbB ^ b_xor[jp]), bl[jp]);
            }
#pragma unroll
            for (int i = 0; i < 4; i++)
#pragma unroll
                for (int j = 0; j < 4; j++)
                    mma16816(acc[i][j], ah[i], bh[j >> 1][(j & 1) * 2], bh[j >> 1][(j & 1) * 2 + 1]);
#pragma unroll
            for (int i = 0; i < 4; i++)
#pragma unroll
                for (int j = 0; j < 4; j++)
                    mma16816(acc[i][j], ah[i], bl[j >> 1][(j & 1) * 2], bl[j >> 1][(j & 1) * 2 + 1]);
#pragma unroll
            for (int i = 0; i < 4; i++)
#pragma unroll
                for (int j = 0; j < 4; j++)
                    mma16816(acc[i][j], al[i], bh[j >> 1][(j & 1) * 2], bh[j >> 1][(j & 1) * 2 + 1]);
        }
        __syncthreads();

        if (more) {
            const uint32_t stn = sb + (uint32_t)((c + 1) & 1) * STAGE_SZ;
#pragma unroll
            for (int i = 0; i < 8; i++) {
                __nv_bfloat16 h0, h1, h2, h3, l0, l1, l2, l3;
                split_bf16(pa[i].x, h0, l0); split_bf16(pa[i].y, h1, l1);
                split_bf16(pa[i].z, h2, l2); split_bf16(pa[i].w, h3, l3);
                asm volatile("st.shared.v2.b32 [%0], {%1, %2};"
                    :: "r"(stn + a_soff[i]), "r"(pack_bf16(h0, h1)), "r"(pack_bf16(h2, h3)) : "memory");
                asm volatile("st.shared.v2.b32 [%0], {%1, %2};"
                    :: "r"(stn + TILE_SZ + a_soff[i]), "r"(pack_bf16(l0, l1)), "r"(pack_bf16(l2, l3)) : "memory");
            }
#pragma unroll
            for (int i = 0; i < 4; i++) {
                asm volatile("st.shared.v4.b32 [%0], {%1, %2, %3, %4};"
                    :: "r"(stn + 2 * TILE_SZ + b_soff[i]), "r"(pbh[i].x), "r"(pbh[i].y), "r"(pbh[i].z), "r"(pbh[i].w) : "memory");
                asm volatile("st.shared.v4.b32 [%0], {%1, %2, %3, %4};"
                    :: "r"(stn + 3 * TILE_SZ + b_soff[i]), "r"(pbl[i].x), "r"(pbl[i].y), "r"(pbl[i].z), "r"(pbl[i].w) : "memory");
            }
            __syncthreads();
        }
    }

    // ---- epilogue ----
    const int cr  = lane >> 2;
    const int cc2 = (lane & 3) * 2;
#pragma unroll
    for (int i = 0; i < 4; i++) {
#pragma unroll
        for (int j = 0; j < 4; j++) {
            const int col  = wn + j * 8 + cc2;
            const int gcol = col0 + col;
            const int r0 = row0 + wm + i * 16 + cr;
            float v0 = acc[i][j][0] + sbias[col];
            float v1 = acc[i][j][1] + sbias[col + 1];
            float v2 = acc[i][j][2] + sbias[col];
            float v3 = acc[i][j][3] + sbias[col + 1];
            if (gcol < scale_cols) { v0 *= 0.125f; v1 *= 0.125f; v2 *= 0.125f; v3 *= 0.125f; }
            if (Ch) {
                uint32_t hp, lp;
                pack_split(v0, v1, hp, lp);
                *(uint32_t*)&Ch[(size_t)r0 * N + gcol] = hp;
                *(uint32_t*)&Cl[(size_t)r0 * N + gcol] = lp;
                pack_split(v2, v3, hp, lp);
                *(uint32_t*)&Ch[(size_t)(r0 + 8) * N + gcol] = hp;
                *(uint32_t*)&Cl[(size_t)(r0 + 8) * N + gcol] = lp;
            } else {
                *(float2*)&Cf[(size_t)r0 * N + gcol]       = make_float2(v0, v1);
                *(float2*)&Cf[(size_t)(r0 + 8) * N + gcol] = make_float2(v2, v3);
            }
        }
    }
}

// ============================================================================
// HMMA flash attention (round-10 winner, byte-identical): CTA = 128 q-rows x
// (head, batch), 8 warps x 16 rows, K/V tiles of 64 rows, double-buffered:
// smem = Q 32K + 2 x 32K = 96K -> 2 CTAs/SM. Output fp32 [B,S,E].
// ============================================================================
#define ATT_STAGE 32768
#define ATT_SMEM  (32768 + 2 * ATT_STAGE)  /* 98304 */
#define KT_ROWS   64

__global__ __launch_bounds__(256, 2)
void attn_mma_kernel(const __nv_bfloat16* __restrict__ QKVh,
                     const __nv_bfloat16* __restrict__ QKVl,
                     float* __restrict__ out) {
    extern __shared__ char smem[];
    const uint32_t sb = smem_to_u32(smem);
    const int tid = threadIdx.x, wid = tid >> 5, lane = tid & 31;
    const int qt = blockIdx.x, h = blockIdx.y, b = blockIdx.z;
    const size_t rowbase = (size_t)b * S_LEN;
    const int hcol = h * HDIM;

    const uint32_t sQH = sb, sQL = sb + 16384;

    // ---- Q producer: 2 threads/row, 4 x 16B each ----
    {
        const int p_r  = tid >> 1;
        const int p_cb = (tid & 1) * 64;
        const size_t grow = (rowbase + qt * 128 + p_r) * E3 + hcol;
#pragma unroll
        for (int i = 0; i < 4; i++) {
            const uint32_t bc  = (uint32_t)(p_cb + i * 16);
            const uint32_t off = (uint32_t)(p_r * 128) + (bc ^ (((uint32_t)p_r & 7) << 4));
            cp_async16(sQH + off, QKVh + grow + (bc >> 1));
            cp_async16(sQL + off, QKVl + grow + (bc >> 1));
        }
    }
    // ---- K/V producer: 4 threads/row, 2 x 16B per tile each ----
    const int q_r  = tid >> 2;
    const int q_cb = (tid & 3) * 32;
    auto issue_kv = [&](int kt) {
        const uint32_t st = sb + 32768 + (uint32_t)(kt & 1) * ATT_STAGE;
        const size_t growK = (rowbase + kt * KT_ROWS + q_r) * E3 + (EMBED + hcol);
        const size_t growV = growK + EMBED;
#pragma unroll
        for (int i = 0; i < 2; i++) {
            const uint32_t bc  = (uint32_t)(q_cb + i * 16);
            const uint32_t off = (uint32_t)(q_r * 128) + (bc ^ (((uint32_t)q_r & 7) << 4));
            cp_async16(st + off,         QKVh + growK + (bc >> 1));
            cp_async16(st + 8192 + off,  QKVl + growK + (bc >> 1));
            cp_async16(st + 16384 + off, QKVh + growV + (bc >> 1));
            cp_async16(st + 24576 + off, QKVl + growV + (bc >> 1));
        }
    };
    issue_kv(0);
    CP_COMMIT();

    // ---- consumer addressing ----
    const int wm = wid * 16;
    const int a_row = wm + (lane & 15);
    const uint32_t a_rowoff = (uint32_t)(a_row * 128);
    const uint32_t a_xor    = ((uint32_t)a_row & 7) << 4;
    const uint32_t a_kbb    = (uint32_t)((lane >> 4) * 16);
    const int b_nr = (lane & 7) | ((lane >> 4) << 3);
    const uint32_t b_kbb = (uint32_t)(((lane >> 3) & 1) * 16);
    const uint32_t b_xor = ((uint32_t)lane & 7) << 4;
    const int v_r = ((lane >> 3) & 1) * 8 + (lane & 7);
    const uint32_t v_cbb = (uint32_t)((lane >> 4) * 16);
    const uint32_t v_xor = ((uint32_t)lane & 7) << 4;

    float m0 = -1e30f, m1 = -1e30f, l0 = 0.f, l1 = 0.f;
    float o[8][4];
#pragma unroll
    for (int j = 0; j < 8; j++)
#pragma unroll
        for (int q = 0; q < 4; q++) o[j][q] = 0.f;

    for (int kt = 0; kt < S_LEN / KT_ROWS; kt++) {
        const uint32_t st = sb + 32768 + (uint32_t)(kt & 1) * ATT_STAGE;
        if (kt + 1 < S_LEN / KT_ROWS) {
            issue_kv(kt + 1);
            CP_COMMIT();
            asm volatile("cp.async.wait_group 1;" ::: "memory");
        } else {
            asm volatile("cp.async.wait_group 0;" ::: "memory");
        }
        __syncthreads();

        // === S = Q @ K^T (3-term split) ===
        float s[8][4];
#pragma unroll
        for (int j = 0; j < 8; j++)
#pragma unroll
            for (int q = 0; q < 4; q++) s[j][q] = 0.f;

#pragma unroll
        for (int ks = 0; ks < 4; ks++) {
            const uint32_t akb = (uint32_t)(ks * 32) + a_kbb;
            uint32_t qh[4], ql[4];
            ldsm4(sQH + a_rowoff + (akb ^ a_xor), qh);
            ldsm4(sQL + a_rowoff + (akb ^ a_xor), ql);
            const uint32_t kcb = ((uint32_t)(ks * 32) + b_kbb) ^ b_xor;
#pragma unroll
            for (int jp = 0; jp < 4; jp++) {
                const uint32_t roff = (uint32_t)((jp * 16 + b_nr) * 128);
                uint32_t kh[4], kl[4];
                ldsm4(st + roff + kcb, kh);
                ldsm4(st + 8192 + roff + kcb, kl);
                mma16816(s[2 * jp],     qh, kh[0], kh[1]);
                mma16816(s[2 * jp + 1], qh, kh[2], kh[3]);
                mma16816(s[2 * jp],     qh, kl[0], kl[1]);
                mma16816(s[2 * jp + 1], qh, kl[2], kl[3]);
                mma16816(s[2 * jp],     ql, kh[0], kh[1]);
                mma16816(s[2 * jp + 1], ql, kh[2], kh[3]);
            }
        }

        // === online softmax ===
        float mx0 = -1e30f, mx1 = -1e30f;
#pragma unroll
        for (int j = 0; j < 8; j++) {
            mx0 = fmaxf(mx0, fmaxf(s[j][0], s[j][1]));
            mx1 = fmaxf(mx1, fmaxf(s[j][2], s[j][3]));
        }
        mx0 = fmaxf(mx0, __shfl_xor_sync(0xffffffffu, mx0, 1));
        mx0 = fmaxf(mx0, __shfl_xor_sync(0xffffffffu, mx0, 2));
        mx1 = fmaxf(mx1, __shfl_xor_sync(0xffffffffu, mx1, 1));
        mx1 = fmaxf(mx1, __shfl_xor_sync(0xffffffffu, mx1, 2));
        const float mn0 = fmaxf(m0, mx0), mn1 = fmaxf(m1, mx1);
        const float al0 = __expf(m0 - mn0), al1 = __expf(m1 - mn1);
#pragma unroll
        for (int j = 0; j < 8; j++) {
            o[j][0] *= al0; o[j][1] *= al0;
            o[j][2] *= al1; o[j][3] *= al1;
        }
        float sum0 = 0.f, sum1 = 0.f;
#pragma unroll
        for (int j = 0; j < 8; j++) {
            s[j][0] = __expf(s[j][0] - mn0);
            s[j][1] = __expf(s[j][1] - mn0);
            s[j][2] = __expf(s[j][2] - mn1);
            s[j][3] = __expf(s[j][3] - mn1);
            sum0 += s[j][0] + s[j][1];
            sum1 += s[j][2] + s[j][3];
        }
        sum0 += __shfl_xor_sync(0xffffffffu, sum0, 1);
        sum0 += __shfl_xor_sync(0xffffffffu, sum0, 2);
        sum1 += __shfl_xor_sync(0xffffffffu, sum1, 1);
        sum1 += __shfl_xor_sync(0xffffffffu, sum1, 2);
        l0 = l0 * al0 + sum0;
        l1 = l1 * al1 + sum1;
        m0 = mn0; m1 = mn1;

        // === O += P @ V (3-term split) ===
#pragma unroll
        for (int kk = 0; kk < 4; kk++) {
            uint32_t aph[4], apl[4];
            pack_split(s[2 * kk][0],     s[2 * kk][1],     aph[0], apl[0]);
            pack_split(s[2 * kk][2],     s[2 * kk][3],     aph[1], apl[1]);
            pack_split(s[2 * kk + 1][0], s[2 * kk + 1][1], aph[2], apl[2]);
            pack_split(s[2 * kk + 1][2], s[2 * kk + 1][3], aph[3], apl[3]);
            const uint32_t vroff = (uint32_t)((kk * 16 + v_r) * 128);
#pragma unroll
            for (int jn = 0; jn < 4; jn++) {
                const uint32_t vcb = ((uint32_t)(jn * 32) + v_cbb) ^ v_xor;
                uint32_t vh[4], vl[4];
                ldsm4t(st + 16384 + vroff + vcb, vh);
                ldsm4t(st + 24576 + vroff + vcb, vl);
                mma16816(o[2 * jn],     aph, vh[0], vh[1]);
                mma16816(o[2 * jn + 1], aph, vh[2], vh[3]);
                mma16816(o[2 * jn],     aph, vl[0], vl[1]);
                mma16816(o[2 * jn + 1], aph, vl[2], vl[3]);
                mma16816(o[2 * jn],     apl, vh[0], vh[1]);
                mma16816(o[2 * jn + 1], apl, vh[2], vh[3]);
            }
        }
        __syncthreads();
    }

    // === epilogue: normalize, write fp32 [B,S,E] with head offset ===
    const int gr  = lane >> 2;
    const int cc2 = (lane & 3) * 2;
    const float inv0 = 1.f / l0, inv1 = 1.f / l1;
    const size_t r0 = rowbase + (size_t)(qt * 128 + wm + gr);
#pragma unroll
    for (int j = 0; j < 8; j++) {
        const int col = hcol + j * 8 + cc2;
        *(float2*)&out[r0 * EMBED + col] =
            make_float2(o[j][0] * inv0, o[j][1] * inv0);
        *(float2*)&out[(r0 + 8) * EMBED + col] =
            make_float2(o[j][2] * inv1, o[j][3] * inv1);
    }
}

// ============================================================================
// Launch
// ============================================================================
extern "C" void kernel_launch(void* const* d_in, const int* in_sizes, int n_in,
                              void* d_out, int out_size) {
    const float* x     = (const float*)d_in[0];
    const float* W_qkv = (const float*)d_in[1];
    const float* b_qkv = (const float*)d_in[2];
    const float* W_out = (const float*)d_in[3];
    const float* b_out = (const float*)d_in[4];
    float* out = (float*)d_out;

    float* attn_ptr;
    cudaGetSymbolAddress((void**)&attn_ptr, g_attn);
    __nv_bfloat16 *qkvh, *qkvl, *wq_hi, *wq_lo, *wo_hi, *wo_lo;
    cudaGetSymbolAddress((void**)&qkvh, g_qkvh);
    cudaGetSymbolAddress((void**)&qkvl, g_qkvl);
    cudaGetSymbolAddress((void**)&wq_hi, g_wq_hi);
    cudaGetSymbolAddress((void**)&wq_lo, g_wq_lo);
    cudaGetSymbolAddress((void**)&wo_hi, g_wo_hi);
    cudaGetSymbolAddress((void**)&wo_lo, g_wo_lo);

    cudaFuncSetAttribute(tc_gemm_bias, cudaFuncAttributeMaxDynamicSharedMemorySize, SM_GEMM_TOTAL);
    cudaFuncSetAttribute(attn_mma_kernel, cudaFuncAttributeMaxDynamicSharedMemorySize, ATT_SMEM);

    // 0) fused weight transpose + bf16 split (both weights, one launch)
    wtrans_split2_kernel<<<dim3(E3 / 32, EMBED / 32, 2), 256>>>(
        W_qkv, wq_hi, wq_lo, W_out, wo_hi, wo_lo);

    // 1) QKV projection (fp32 x input) -> pre-split bf16, Q pre-scaled by 0.125
    tc_gemm_bias<<<dim3(E3 / BN, M_TOTAL / BM), 256, SM_GEMM_TOTAL>>>(
        x, wq_hi, wq_lo, b_qkv, nullptr, qkvh, qkvl, M_TOTAL, E3, EMBED, EMBED);

    // 2) Attention (2 CTAs/SM) -> fp32
    dim3 g2(S_LEN / 128, HEADS, BATCH);
    attn_mma_kernel<<<g2, 256, ATT_SMEM>>>(qkvh, qkvl, attn_ptr);

    // 3) Output projection (fp32 attn input) -> fp32 final output
    tc_gemm_bias<<<dim3(EMBED / BN, M_TOTAL / BM), 256, SM_GEMM_TOTAL>>>(
        attn_ptr, wo_hi, wo_lo, b_out, out, nullptr, nullptr, M_TOTAL, EMBED, EMBED, 0);
}

// round 15
// speedup vs baseline: 1.5032x; 1.0466x over previous
#include <cuda_runtime.h>
#include <cuda_bf16.h>
#include <cstdint>

// ============================================================================
// Problem constants
// ============================================================================
#define S_LEN   2048
#define EMBED   1024
#define E3      3072
#define HEADS   16
#define HDIM    64
#define BATCH   4
#define M_TOTAL (BATCH * S_LEN) /* 8192 */

// Scratch (allocation-free contract)
__device__ __align__(16) __nv_bfloat16 g_xh[(size_t)M_TOTAL * EMBED];
__device__ __align__(16) __nv_bfloat16 g_xl[(size_t)M_TOTAL * EMBED];
__device__ __align__(16) __nv_bfloat16 g_qkvh[(size_t)M_TOTAL * E3];
__device__ __align__(16) __nv_bfloat16 g_qkvl[(size_t)M_TOTAL * E3];
__device__ float g_attn[(size_t)M_TOTAL * EMBED];
__device__ __align__(16) __nv_bfloat16 g_wq_hi[(size_t)E3 * EMBED];
__device__ __align__(16) __nv_bfloat16 g_wq_lo[(size_t)E3 * EMBED];
__device__ __align__(16) __nv_bfloat16 g_wo_hi[(size_t)EMBED * EMBED];
__device__ __align__(16) __nv_bfloat16 g_wo_lo[(size_t)EMBED * EMBED];

// ============================================================================
// Helpers
// ============================================================================
__device__ __forceinline__ uint32_t smem_to_u32(const void* smem_ptr) {
    uint32_t addr;
    asm("{ .reg .u64 tmp; cvta.to.shared.u64 tmp, %1; cvt.u32.u64 %0, tmp; }"
        : "=r"(addr) : "l"(smem_ptr));
    return addr;
}

#define SMEM_SWIZZLE_128B(byte_offset) \
    ((byte_offset) ^ (((byte_offset) >> 3) & 0x70))

__device__ __forceinline__ void ldsm4(uint32_t addr, uint32_t r[4]) {
    asm volatile("ldmatrix.sync.aligned.m8n8.x4.shared.b16 {%0,%1,%2,%3}, [%4];"
                 : "=r"(r[0]), "=r"(r[1]), "=r"(r[2]), "=r"(r[3]) : "r"(addr));
}

__device__ __forceinline__ void ldsm4t(uint32_t addr, uint32_t r[4]) {
    asm volatile("ldmatrix.sync.aligned.m8n8.x4.trans.shared.b16 {%0,%1,%2,%3}, [%4];"
                 : "=r"(r[0]), "=r"(r[1]), "=r"(r[2]), "=r"(r[3]) : "r"(addr));
}

__device__ __forceinline__ void mma16816(float c[4], const uint32_t a[4],
                                         uint32_t b0, uint32_t b1) {
    asm volatile(
        "mma.sync.aligned.m16n8k16.row.col.f32.bf16.bf16.f32 "
        "{%0,%1,%2,%3}, {%4,%5,%6,%7}, {%8,%9}, {%0,%1,%2,%3};"
        : "+f"(c[0]), "+f"(c[1]), "+f"(c[2]), "+f"(c[3])
        : "r"(a[0]), "r"(a[1]), "r"(a[2]), "r"(a[3]), "r"(b0), "r"(b1));
}

__device__ __forceinline__ void cp_async16(uint32_t saddr, const void* gptr) {
    asm volatile("cp.async.cg.shared.global [%0], [%1], 16;"
                 :: "r"(saddr), "l"(gptr) : "memory");
}
#define CP_COMMIT() asm volatile("cp.async.commit_group;" ::: "memory")
#define CP_WAIT(n)  asm volatile("cp.async.wait_group %0;" :: "n"(n) : "memory")

__device__ __forceinline__ void split_bf16(float v, __nv_bfloat16& h, __nv_bfloat16& l) {
    h = __float2bfloat16(v);
    l = __float2bfloat16(v - __bfloat162float(h));
}

__device__ __forceinline__ uint32_t pack_bf16(__nv_bfloat16 a, __nv_bfloat16 b) {
    __nv_bfloat162 t = __halves2bfloat162(a, b);
    return *reinterpret_cast<uint32_t*>(&t);
}

// pack (x,y) -> bf16x2 hi-word, residual pair -> lo-word
__device__ __forceinline__ void pack_split(float x, float y, uint32_t& hp, uint32_t& lp) {
    asm("cvt.rn.bf16x2.f32 %0, %1, %2;" : "=r"(hp) : "f"(y), "f"(x));
    const float hx = __uint_as_float(hp << 16);
    const float hy = __uint_as_float(hp & 0xffff0000u);
    const float rx = x - hx, ry = y - hy;
    asm("cvt.rn.bf16x2.f32 %0, %1, %2;" : "=r"(lp) : "f"(ry), "f"(rx));
}

// ============================================================================
// Prep (fused): transpose W[K,N] -> Wt[N,K], split fp32 into bf16 hi + lo.
// blockIdx.z = 0 -> W_qkv (N=3072), 1 -> W_out (N=1024).
// ============================================================================
__global__ __launch_bounds__(256)
void wtrans_split2_kernel(const float* __restrict__ W0, __nv_bfloat16* __restrict__ Th0,
                          __nv_bfloat16* __restrict__ Tl0,
                          const float* __restrict__ W1, __nv_bfloat16* __restrict__ Th1,
                          __nv_bfloat16* __restrict__ Tl1) {
    const int z = blockIdx.z;
    const int N = z ? EMBED : E3;
    const int n0 = blockIdx.x * 32, k0 = blockIdx.y * 32;
    if (n0 >= N) return;
    const float* W = z ? W1 : W0;
    __nv_bfloat16* Th = z ? Th1 : Th0;
    __nv_bfloat16* Tl = z ? Tl1 : Tl0;
    const int K = EMBED;

    __shared__ float t[32][33];
    const int tid = threadIdx.x;
    const int c = tid & 31, r = tid >> 5;
#pragma unroll
    for (int i = 0; i < 4; i++)
        t[r + i * 8][c] = W[(size_t)(k0 + r + i * 8) * N + n0 + c];
    __syncthreads();
    const int n  = tid >> 3;
    const int kq = (tid & 7) * 4;
    __nv_bfloat16 h[4], l[4];
#pragma unroll
    for (int j = 0; j < 4; j++) split_bf16(t[kq + j][n], h[j], l[j]);
    const size_t o = (size_t)(n0 + n) * K + k0 + kq;
    *(__nv_bfloat162*)&Th[o]     = __halves2bfloat162(h[0], h[1]);
    *(__nv_bfloat162*)&Th[o + 2] = __halves2bfloat162(h[2], h[3]);
    *(__nv_bfloat162*)&Tl[o]     = __halves2bfloat162(l[0], l[1]);
    *(__nv_bfloat162*)&Tl[o + 2] = __halves2bfloat162(l[2], l[3]);
}

// ============================================================================
// Prep 2: elementwise fp32 -> bf16 hi/lo split (for x)
// ============================================================================
__global__ __launch_bounds__(256)
void fsplit_kernel(const float* __restrict__ X, __nv_bfloat16* __restrict__ Xh,
                   __nv_bfloat16* __restrict__ Xl) {
    const size_t idx = (size_t)blockIdx.x * 256 + threadIdx.x;
    const float4 v = ((const float4*)X)[idx];
    uint32_t h0, l0, h1, l1;
    pack_split(v.x, v.y, h0, l0);
    pack_split(v.z, v.w, h1, l1);
    ((uint2*)Xh)[idx] = make_uint2(h0, h1);
    ((uint2*)Xl)[idx] = make_uint2(l0, l1);
}

// ============================================================================
// QKV GEMM, 2-CTA/SM: CTA 128(M) x 96(N), 192 threads (6 warps, 2x3),
// warp tile 64x32 (measured-best inner loop, byte-identical), BK=64,
// all-bf16 cp.async 2-stage producer. Stage 56KB, smem 112KB -> 2 CTAs/SM
// with 168-reg budget (no clamp). Output pre-split bf16, Q scaled 0.125.
// ============================================================================
#define QBM 128
#define QBN 96
#define QA_TILE 16384           /* 128 x 128B per h/l */
#define QB_TILE 12288           /* 96 x 128B per h/l */
#define QOFF_AH 0
#define QOFF_AL QA_TILE
#define QOFF_BH (2 * QA_TILE)
#define QOFF_BL (2 * QA_TILE + QB_TILE)
#define QSTAGE_SZ  (2 * QA_TILE + 2 * QB_TILE)  /* 57344 */
#define SM_QKV_TOTAL (2 * QSTAGE_SZ)            /* 114688 */

__global__ __launch_bounds__(192, 2)
void tc_gemm_qkv(const __nv_bfloat16* __restrict__ Ah, const __nv_bfloat16* __restrict__ Al,
                 const __nv_bfloat16* __restrict__ Bth, const __nv_bfloat16* __restrict__ Btl,
                 const float* __restrict__ bias,
                 __nv_bfloat16* __restrict__ Ch, __nv_bfloat16* __restrict__ Cl,
                 int M, int N, int K, int scale_cols) {
    extern __shared__ char smem[];
    const uint32_t sb = smem_to_u32(smem);
    const int tid  = threadIdx.x;
    const int wid  = tid >> 5;
    const int lane = tid & 31;
    const int row0 = blockIdx.y * QBM;
    const int col0 = blockIdx.x * QBN;
    const int nchunks = K / 64;

    // ---- producer: flat 16B-chunk loops.
    // A region: 2048 chunks (rows 0..255 = AH rows then AL rows, 8 chunks/row)
    // B region: 1536 chunks (rows 0..191 = BH rows then BL rows, 8 chunks/row)
    auto issue = [&](int c) {
        const uint32_t st = sb + (uint32_t)(c & 1) * QSTAGE_SZ;
        const int k0 = c * 64;
#pragma unroll
        for (int it = 0; it < 11; it++) {
            const int idx = tid + it * 192;
            if (it == 10 && idx >= 2048) break;
            const int row2 = idx >> 3;          // 0..255
            const int ch   = idx & 7;
            const int r    = row2 & 127;
            const __nv_bfloat16* g = (row2 < 128)
                ? (Ah + (size_t)(row0 + r) * K) : (Al + (size_t)(row0 + r) * K);
            const uint32_t soff = (uint32_t)((row2 < 128 ? QOFF_AH : QOFF_AL) + r * 128)
                + (((uint32_t)(ch * 16)) ^ (((uint32_t)r & 7) << 4));
            cp_async16(st + soff, g + k0 + ch * 8);
        }
#pragma unroll
        for (int it = 0; it < 8; it++) {
            const int idx = tid + it * 192;     // < 1536 always
            const int row2 = idx >> 3;          // 0..191
            const int ch   = idx & 7;
            const int r    = (row2 < 96) ? row2 : row2 - 96;
            const __nv_bfloat16* g = (row2 < 96)
                ? (Bth + (size_t)(col0 + r) * K) : (Btl + (size_t)(col0 + r) * K);
            const uint32_t soff = (uint32_t)((row2 < 96 ? QOFF_BH : QOFF_BL) + r * 128)
                + (((uint32_t)(ch * 16)) ^ (((uint32_t)r & 7) << 4));
            cp_async16(st + soff, g + k0 + ch * 8);
        }
        CP_COMMIT();
    };

    // ---- consumer: 2x3 warp grid, warp tile 64x32 ----
    const int wm = (wid / 3) * 64;
    const int wn = (wid % 3) * 32;
    const int a_r    = lane & 15;
    const int a_half = lane >> 4;
    const int b_nr   = (lane & 7) | ((lane >> 4) << 3);
    const int b_kh   = (lane >> 3) & 1;

    uint32_t a_rowoff[4], a_xor[4], b_rowoff[2], b_xor[2];
#pragma unroll
    for (int i = 0; i < 4; i++) {
        const int r = wm + i * 16 + a_r;
        a_rowoff[i] = (uint32_t)(r * 128);
        a_xor[i]    = (uint32_t)((r & 7) << 4);
    }
#pragma unroll
    for (int jp = 0; jp < 2; jp++) {
        const int r = wn + jp * 16 + b_nr;
        b_rowoff[jp] = (uint32_t)(r * 128);
        b_xor[jp]    = (uint32_t)((r & 7) << 4);
    }
    const uint32_t a_kbb = (uint32_t)(a_half * 16);
    const uint32_t b_kbb = (uint32_t)(b_kh * 16);

    float acc[4][4][4];
#pragma unroll
    for (int i = 0; i < 4; i++)
#pragma unroll
        for (int j = 0; j < 4; j++)
#pragma unroll
            for (int q = 0; q < 4; q++) acc[i][j][q] = 0.f;

    issue(0);
    issue(1);

    for (int c = 0; c < nchunks; c++) {
        if (c + 1 < nchunks) { CP_WAIT(1); } else { CP_WAIT(0); }
        __syncthreads();

        const uint32_t st = sb + (uint32_t)(c & 1) * QSTAGE_SZ;
#pragma unroll
        for (int ks = 0; ks < 4; ks++) {
            const uint32_t kbA = (uint32_t)(ks * 32) + a_kbb;
            const uint32_t kbB = (uint32_t)(ks * 32) + b_kbb;
            uint32_t ah[4][4], al[4][4], bh[2][4], bl[2][4];
#pragma unroll
            for (int i = 0; i < 4; i++) {
                ldsm4(st + QOFF_AH + a_rowoff[i] + (kbA ^ a_xor[i]), ah[i]);
                ldsm4(st + QOFF_AL + a_rowoff[i] + (kbA ^ a_xor[i]), al[i]);
            }
#pragma unroll
            for (int jp = 0; jp < 2; jp++) {
                ldsm4(st + QOFF_BH + b_rowoff[jp] + (kbB ^ b_xor[jp]), bh[jp]);
                ldsm4(st + QOFF_BL + b_rowoff[jp] + (kbB ^ b_xor[jp]), bl[jp]);
            }
#pragma unroll
            for (int i = 0; i < 4; i++)
#pragma unroll
                for (int j = 0; j < 4; j++)
                    mma16816(acc[i][j], ah[i], bh[j >> 1][(j & 1) * 2], bh[j >> 1][(j & 1) * 2 + 1]);
#pragma unroll
            for (int i = 0; i < 4; i++)
#pragma unroll
                for (int j = 0; j < 4; j++)
                    mma16816(acc[i][j], ah[i], bl[j >> 1][(j & 1) * 2], bl[j >> 1][(j & 1) * 2 + 1]);
#pragma unroll
            for (int i = 0; i < 4; i++)
#pragma unroll
                for (int j = 0; j < 4; j++)
                    mma16816(acc[i][j], al[i], bh[j >> 1][(j & 1) * 2], bh[j >> 1][(j & 1) * 2 + 1]);
        }
        __syncthreads();
        if (c + 2 < nchunks) issue(c + 2);
    }

    // ---- epilogue (bias direct from gmem; pre-split bf16 out) ----
    const int cr  = lane >> 2;
    const int cc2 = (lane & 3) * 2;
#pragma unroll
    for (int i = 0; i < 4; i++) {
#pragma unroll
        for (int j = 0; j < 4; j++) {
            const int gcol = col0 + wn + j * 8 + cc2;
            const int r0 = row0 + wm + i * 16 + cr;
            const float b0 = __ldg(&bias[gcol]), b1 = __ldg(&bias[gcol + 1]);
            float v0 = acc[i][j][0] + b0;
            float v1 = acc[i][j][1] + b1;
            float v2 = acc[i][j][2] + b0;
            float v3 = acc[i][j][3] + b1;
            if (gcol < scale_cols) { v0 *= 0.125f; v1 *= 0.125f; v2 *= 0.125f; v3 *= 0.125f; }
            uint32_t hp, lp;
            pack_split(v0, v1, hp, lp);
            *(uint32_t*)&Ch[(size_t)r0 * N + gcol] = hp;
            *(uint32_t*)&Cl[(size_t)r0 * N + gcol] = lp;
            pack_split(v2, v3, hp, lp);
            *(uint32_t*)&Ch[(size_t)(r0 + 8) * N + gcol] = hp;
            *(uint32_t*)&Cl[(size_t)(r0 + 8) * N + gcol] = lp;
        }
    }
}

// ============================================================================
// Out-projection GEMM (round-14 banked kernel, byte-identical):
// C = A[M,K](fp32) @ Bt[N,K](bf16 hi/lo) + bias -> fp32.
// CTA 128x128, BK=64, 8 warps, warp tile 64x32, register prefetch producer.
// ============================================================================
#define BM 128
#define BN 128
#define BK 64
#define TILE_SZ   16384
#define STAGE_SZ  (4 * TILE_SZ)
#define SM_GEMM_TOTAL (2 * STAGE_SZ)

__global__ __launch_bounds__(256, 1)
void tc_gemm_bias(const float* __restrict__ A, const __nv_bfloat16* __restrict__ Bth,
                  const __nv_bfloat16* __restrict__ Btl, const float* __restrict__ bias,
                  float* __restrict__ Cf, int M, int N, int K) {
    extern __shared__ char smem[];
    __shared__ float sbias[BN];
    const uint32_t sb = smem_to_u32(smem);
    const int tid  = threadIdx.x;
    const int wid  = tid >> 5;
    const int lane = tid & 31;
    const int row0 = blockIdx.y * BM;
    const int col0 = blockIdx.x * BN;
    const int nchunks = K / BK;

    if (tid < BN) sbias[tid] = bias[col0 + tid];

    const int a_kq = (tid & 15) * 4;
    const int a_m0 = tid >> 4;
    const int b_kg = (tid & 7) * 8;
    const int b_n0 = tid >> 3;

    uint32_t a_soff[8], b_soff[4];
#pragma unroll
    for (int i = 0; i < 8; i++) {
        const int m = a_m0 + i * 16;
        a_soff[i] = SMEM_SWIZZLE_128B((uint32_t)(m * 128 + a_kq * 2));
    }
#pragma unroll
    for (int i = 0; i < 4; i++) {
        const int n = b_n0 + i * 32;
        b_soff[i] = SMEM_SWIZZLE_128B((uint32_t)(n * 128 + b_kg * 2));
    }

    const int wm = (wid >> 2) * 64;
    const int wn = (wid & 3) * 32;
    const int a_r    = lane & 15;
    const int a_half = lane >> 4;
    const int b_nr   = (lane & 7) | ((lane >> 4) << 3);
    const int b_kh   = (lane >> 3) & 1;

    uint32_t a_rowoff[4], a_xor[4], b_rowoff[2], b_xor[2];
#pragma unroll
    for (int i = 0; i < 4; i++) {
        const int r = wm + i * 16 + a_r;
        a_rowoff[i] = (uint32_t)(r * 128);
        a_xor[i]    = (uint32_t)((r & 7) << 4);
    }
#pragma unroll
    for (int jp = 0; jp < 2; jp++) {
        const int r = wn + jp * 16 + b_nr;
        b_rowoff[jp] = (uint32_t)(r * 128);
        b_xor[jp]    = (uint32_t)((r & 7) << 4);
    }
    const uint32_t a_kbb = (uint32_t)(a_half * 16);
    const uint32_t b_kbb = (uint32_t)(b_kh * 16);

    float acc[4][4][4];
#pragma unroll
    for (int i = 0; i < 4; i++)
#pragma unroll
        for (int j = 0; j < 4; j++)
#pragma unroll
            for (int q = 0; q < 4; q++) acc[i][j][q] = 0.f;

    {
        const uint32_t st = sb;
#pragma unroll
        for (int i = 0; i < 8; i++) {
            const int m = a_m0 + i * 16;
            const float4 v = *(const float4*)&A[(size_t)(row0 + m) * K + a_kq];
            __nv_bfloat16 h0, h1, h2, h3, l0, l1, l2, l3;
            split_bf16(v.x, h0, l0); split_bf16(v.y, h1, l1);
            split_bf16(v.z, h2, l2); split_bf16(v.w, h3, l3);
            asm volatile("st.shared.v2.b32 [%0], {%1, %2};"
                :: "r"(st + a_soff[i]), "r"(pack_bf16(h0, h1)), "r"(pack_bf16(h2, h3)) : "memory");
            asm volatile("st.shared.v2.b32 [%0], {%1, %2};"
                :: "r"(st + TILE_SZ + a_soff[i]), "r"(pack_bf16(l0, l1)), "r"(pack_bf16(l2, l3)) : "memory");
        }
#pragma unroll
        for (int i = 0; i < 4; i++) {
            const int n = b_n0 + i * 32;
            const size_t g = (size_t)(col0 + n) * K + b_kg;
            const uint4 vh = *(const uint4*)&Bth[g];
            const uint4 vl = *(const uint4*)&Btl[g];
            asm volatile("st.shared.v4.b32 [%0], {%1, %2, %3, %4};"
                :: "r"(st + 2 * TILE_SZ + b_soff[i]), "r"(vh.x), "r"(vh.y), "r"(vh.z), "r"(vh.w) : "memory");
            asm volatile("st.shared.v4.b32 [%0], {%1, %2, %3, %4};"
                :: "r"(st + 3 * TILE_SZ + b_soff[i]), "r"(vl.x), "r"(vl.y), "r"(vl.z), "r"(vl.w) : "memory");
        }
    }
    __syncthreads();

    for (int c = 0; c < nchunks; c++) {
        const uint32_t st = sb + (uint32_t)(c & 1) * STAGE_SZ;

        float4 pa[8];
        uint4 pbh[4], pbl[4];
        const bool more = (c + 1 < nchunks);
        if (more) {
            const int k0n = (c + 1) * BK;
#pragma unroll
            for (int i = 0; i < 8; i++) {
                const int m = a_m0 + i * 16;
                pa[i] = *(const float4*)&A[(size_t)(row0 + m) * K + k0n + a_kq];
            }
#pragma unroll
            for (int i = 0; i < 4; i++) {
                const int n = b_n0 + i * 32;
                const size_t g = (size_t)(col0 + n) * K + k0n + b_kg;
                pbh[i] = *(const uint4*)&Bth[g];
                pbl[i] = *(const uint4*)&Btl[g];
            }
        }

        const uint32_t stAh = st, stAl = st + TILE_SZ;
        const uint32_t stBh = st + 2 * TILE_SZ, stBl = st + 3 * TILE_SZ;
#pragma unroll
        for (int ks = 0; ks < 4; ks++) {
            const uint32_t kbA = (uint32_t)(ks * 32) + a_kbb;
            const uint32_t kbB = (uint32_t)(ks * 32) + b_kbb;
            uint32_t ah[4][4], al[4][4], bh[2][4], bl[2][4];
#pragma unroll
            for (int i = 0; i < 4; i++) {
                ldsm4(stAh + a_rowoff[i] + (kbA ^ a_xor[i]), ah[i]);
                ldsm4(stAl + a_rowoff[i] + (kbA ^ a_xor[i]), al[i]);
            }
#pragma unroll
            for (int jp = 0; jp < 2; jp++) {
                ldsm4(stBh + b_rowoff[jp] + (kbB ^ b_xor[jp]), bh[jp]);
                ldsm4(stBl + b_rowoff[jp] + (kbB ^ b_xor[jp]), bl[jp]);
            }
#pragma unroll
            for (int i = 0; i < 4; i++)
#pragma unroll
                for (int j = 0; j < 4; j++)
                    mma16816(acc[i][j], ah[i], bh[j >> 1][(j & 1) * 2], bh[j >> 1][(j & 1) * 2 + 1]);
#pragma unroll
            for (int i = 0; i < 4; i++)
#pragma unroll
                for (int j = 0; j < 4; j++)
                    mma16816(acc[i][j], ah[i], bl[j >> 1][(j & 1) * 2], bl[j >> 1][(j & 1) * 2 + 1]);
#pragma unroll
            for (int i = 0; i < 4; i++)
#pragma unroll
                for (int j = 0; j < 4; j++)
                    mma16816(acc[i][j], al[i], bh[j >> 1][(j & 1) * 2], bh[j >> 1][(j & 1) * 2 + 1]);
        }
        __syncthreads();

        if (more) {
            const uint32_t stn = sb + (uint32_t)((c + 1) & 1) * STAGE_SZ;
#pragma unroll
            for (int i = 0; i < 8; i++) {
                __nv_bfloat16 h0, h1, h2, h3, l0, l1, l2, l3;
                split_bf16(pa[i].x, h0, l0); split_bf16(pa[i].y, h1, l1);
                split_bf16(pa[i].z, h2, l2); split_bf16(pa[i].w, h3, l3);
                asm volatile("st.shared.v2.b32 [%0], {%1, %2};"
                    :: "r"(stn + a_soff[i]), "r"(pack_bf16(h0, h1)), "r"(pack_bf16(h2, h3)) : "memory");
                asm volatile("st.shared.v2.b32 [%0], {%1, %2};"
                    :: "r"(stn + TILE_SZ + a_soff[i]), "r"(pack_bf16(l0, l1)), "r"(pack_bf16(l2, l3)) : "memory");
            }
#pragma unroll
            for (int i = 0; i < 4; i++) {
                asm volatile("st.shared.v4.b32 [%0], {%1, %2, %3, %4};"
                    :: "r"(stn + 2 * TILE_SZ + b_soff[i]), "r"(pbh[i].x), "r"(pbh[i].y), "r"(pbh[i].z), "r"(pbh[i].w) : "memory");
                asm volatile("st.shared.v4.b32 [%0], {%1, %2, %3, %4};"
                    :: "r"(stn + 3 * TILE_SZ + b_soff[i]), "r"(pbl[i].x), "r"(pbl[i].y), "r"(pbl[i].z), "r"(pbl[i].w) : "memory");
            }
            __syncthreads();
        }
    }

    // ---- epilogue ----
    const int cr  = lane >> 2;
    const int cc2 = (lane & 3) * 2;
#pragma unroll
    for (int i = 0; i < 4; i++) {
#pragma unroll
        for (int j = 0; j < 4; j++) {
            const int col  = wn + j * 8 + cc2;
            const int gcol = col0 + col;
            const int r0 = row0 + wm + i * 16 + cr;
            float v0 = acc[i][j][0] + sbias[col];
            float v1 = acc[i][j][1] + sbias[col + 1];
            float v2 = acc[i][j][2] + sbias[col];
            float v3 = acc[i][j][3] + sbias[col + 1];
            *(float2*)&Cf[(size_t)r0 * N + gcol]       = make_float2(v0, v1);
            *(float2*)&Cf[(size_t)(r0 + 8) * N + gcol] = make_float2(v2, v3);
        }
    }
}

// ============================================================================
// HMMA flash attention (round-10/14 winner, byte-identical): CTA = 128
// q-rows x (head, batch), 8 warps, K/V tiles of 64 rows, double-buffered:
// smem 96K -> 2 CTAs/SM. Output fp32 [B,S,E].
// ============================================================================
#define ATT_STAGE 32768
#define ATT_SMEM  (32768 + 2 * ATT_STAGE)  /* 98304 */
#define KT_ROWS   64

__global__ __launch_bounds__(256, 2)
void attn_mma_kernel(const __nv_bfloat16* __restrict__ QKVh,
                     const __nv_bfloat16* __restrict__ QKVl,
                     float* __restrict__ out) {
    extern __shared__ char smem[];
    const uint32_t sb = smem_to_u32(smem);
    const int tid = threadIdx.x, wid = tid >> 5, lane = tid & 31;
    const int qt = blockIdx.x, h = blockIdx.y, b = blockIdx.z;
    const size_t rowbase = (size_t)b * S_LEN;
    const int hcol = h * HDIM;

    const uint32_t sQH = sb, sQL = sb + 16384;

    {
        const int p_r  = tid >> 1;
        const int p_cb = (tid & 1) * 64;
        const size_t grow = (rowbase + qt * 128 + p_r) * E3 + hcol;
#pragma unroll
        for (int i = 0; i < 4; i++) {
            const uint32_t bc  = (uint32_t)(p_cb + i * 16);
            const uint32_t off = (uint32_t)(p_r * 128) + (bc ^ (((uint32_t)p_r & 7) << 4));
            cp_async16(sQH + off, QKVh + grow + (bc >> 1));
            cp_async16(sQL + off, QKVl + grow + (bc >> 1));
        }
    }
    const int q_r  = tid >> 2;
    const int q_cb = (tid & 3) * 32;
    auto issue_kv = [&](int kt) {
        const uint32_t st = sb + 32768 + (uint32_t)(kt & 1) * ATT_STAGE;
        const size_t growK = (rowbase + kt * KT_ROWS + q_r) * E3 + (EMBED + hcol);
        const size_t growV = growK + EMBED;
#pragma unroll
        for (int i = 0; i < 2; i++) {
            const uint32_t bc  = (uint32_t)(q_cb + i * 16);
            const uint32_t off = (uint32_t)(q_r * 128) + (bc ^ (((uint32_t)q_r & 7) << 4));
            cp_async16(st + off,         QKVh + growK + (bc >> 1));
            cp_async16(st + 8192 + off,  QKVl + growK + (bc >> 1));
            cp_async16(st + 16384 + off, QKVh + growV + (bc >> 1));
            cp_async16(st + 24576 + off, QKVl + growV + (bc >> 1));
        }
    };
    issue_kv(0);
    CP_COMMIT();

    const int wm = wid * 16;
    const int a_row = wm + (lane & 15);
    const uint32_t a_rowoff = (uint32_t)(a_row * 128);
    const uint32_t a_xor    = ((uint32_t)a_row & 7) << 4;
    const uint32_t a_kbb    = (uint32_t)((lane >> 4) * 16);
    const int b_nr = (lane & 7) | ((lane >> 4) << 3);
    const uint32_t b_kbb = (uint32_t)(((lane >> 3) & 1) * 16);
    const uint32_t b_xor = ((uint32_t)lane & 7) << 4;
    const int v_r = ((lane >> 3) & 1) * 8 + (lane & 7);
    const uint32_t v_cbb = (uint32_t)((lane >> 4) * 16);
    const uint32_t v_xor = ((uint32_t)lane & 7) << 4;

    float m0 = -1e30f, m1 = -1e30f, l0 = 0.f, l1 = 0.f;
    float o[8][4];
#pragma unroll
    for (int j = 0; j < 8; j++)
#pragma unroll
        for (int q = 0; q < 4; q++) o[j][q] = 0.f;

    for (int kt = 0; kt < S_LEN / KT_ROWS; kt++) {
        const uint32_t st = sb + 32768 + (uint32_t)(kt & 1) * ATT_STAGE;
        if (kt + 1 < S_LEN / KT_ROWS) {
            issue_kv(kt + 1);
            CP_COMMIT();
            asm volatile("cp.async.wait_group 1;" ::: "memory");
        } else {
            asm volatile("cp.async.wait_group 0;" ::: "memory");
        }
        __syncthreads();

        float s[8][4];
#pragma unroll
        for (int j = 0; j < 8; j++)
#pragma unroll
            for (int q = 0; q < 4; q++) s[j][q] = 0.f;

#pragma unroll
        for (int ks = 0; ks < 4; ks++) {
            const uint32_t akb = (uint32_t)(ks * 32) + a_kbb;
            uint32_t qh[4], ql[4];
            ldsm4(sQH + a_rowoff + (akb ^ a_xor), qh);
            ldsm4(sQL + a_rowoff + (akb ^ a_xor), ql);
            const uint32_t kcb = ((uint32_t)(ks * 32) + b_kbb) ^ b_xor;
#pragma unroll
            for (int jp = 0; jp < 4; jp++) {
                const uint32_t roff = (uint32_t)((jp * 16 + b_nr) * 128);
                uint32_t kh[4], kl[4];
                ldsm4(st + roff + kcb, kh);
                ldsm4(st + 8192 + roff + kcb, kl);
                mma16816(s[2 * jp],     qh, kh[0], kh[1]);
                mma16816(s[2 * jp + 1], qh, kh[2], kh[3]);
                mma16816(s[2 * jp],     qh, kl[0], kl[1]);
                mma16816(s[2 * jp + 1], qh, kl[2], kl[3]);
                mma16816(s[2 * jp],     ql, kh[0], kh[1]);
                mma16816(s[2 * jp + 1], ql, kh[2], kh[3]);
            }
        }

        float mx0 = -1e30f, mx1 = -1e30f;
#pragma unroll
        for (int j = 0; j < 8; j++) {
            mx0 = fmaxf(mx0, fmaxf(s[j][0], s[j][1]));
            mx1 = fmaxf(mx1, fmaxf(s[j][2], s[j][3]));
        }
        mx0 = fmaxf(mx0, __shfl_xor_sync(0xffffffffu, mx0, 1));
        mx0 = fmaxf(mx0, __shfl_xor_sync(0xffffffffu, mx0, 2));
        mx1 = fmaxf(mx1, __shfl_xor_sync(0xffffffffu, mx1, 1));
        mx1 = fmaxf(mx1, __shfl_xor_sync(0xffffffffu, mx1, 2));
        const float mn0 = fmaxf(m0, mx0), mn1 = fmaxf(m1, mx1);
        const float al0 = __expf(m0 - mn0), al1 = __expf(m1 - mn1);
#pragma unroll
        for (int j = 0; j < 8; j++) {
            o[j][0] *= al0; o[j][1] *= al0;
            o[j][2] *= al1; o[j][3] *= al1;
        }
        float sum0 = 0.f, sum1 = 0.f;
#pragma unroll
        for (int j = 0; j < 8; j++) {
            s[j][0] = __expf(s[j][0] - mn0);
            s[j][1] = __expf(s[j][1] - mn0);
            s[j][2] = __expf(s[j][2] - mn1);
            s[j][3] = __expf(s[j][3] - mn1);
            sum0 += s[j][0] + s[j][1];
            sum1 += s[j][2] + s[j][3];
        }
        sum0 += __shfl_xor_sync(0xffffffffu, sum0, 1);
        sum0 += __shfl_xor_sync(0xffffffffu, sum0, 2);
        sum1 += __shfl_xor_sync(0xffffffffu, sum1, 1);
        sum1 += __shfl_xor_sync(0xffffffffu, sum1, 2);
        l0 = l0 * al0 + sum0;
        l1 = l1 * al1 + sum1;
        m0 = mn0; m1 = mn1;

#pragma unroll
        for (int kk = 0; kk < 4; kk++) {
            uint32_t aph[4], apl[4];
            pack_split(s[2 * kk][0],     s[2 * kk][1],     aph[0], apl[0]);
            pack_split(s[2 * kk][2],     s[2 * kk][3],     aph[1], apl[1]);
            pack_split(s[2 * kk + 1][0], s[2 * kk + 1][1], aph[2], apl[2]);
            pack_split(s[2 * kk + 1][2], s[2 * kk + 1][3], aph[3], apl[3]);
            const uint32_t vroff = (uint32_t)((kk * 16 + v_r) * 128);
#pragma unroll
            for (int jn = 0; jn < 4; jn++) {
                const uint32_t vcb = ((uint32_t)(jn * 32) + v_cbb) ^ v_xor;
                uint32_t vh[4], vl[4];
                ldsm4t(st + 16384 + vroff + vcb, vh);
                ldsm4t(st + 24576 + vroff + vcb, vl);
                mma16816(o[2 * jn],     aph, vh[0], vh[1]);
                mma16816(o[2 * jn + 1], aph, vh[2], vh[3]);
                mma16816(o[2 * jn],     aph, vl[0], vl[1]);
                mma16816(o[2 * jn + 1], aph, vl[2], vl[3]);
                mma16816(o[2 * jn],     apl, vh[0], vh[1]);
                mma16816(o[2 * jn + 1], apl, vh[2], vh[3]);
            }
        }
        __syncthreads();
    }

    const int gr  = lane >> 2;
    const int cc2 = (lane & 3) * 2;
    const float inv0 = 1.f / l0, inv1 = 1.f / l1;
    const size_t r0 = rowbase + (size_t)(qt * 128 + wm + gr);
#pragma unroll
    for (int j = 0; j < 8; j++) {
        const int col = hcol + j * 8 + cc2;
        *(float2*)&out[r0 * EMBED + col] =
            make_float2(o[j][0] * inv0, o[j][1] * inv0);
        *(float2*)&out[(r0 + 8) * EMBED + col] =
            make_float2(o[j][2] * inv1, o[j][3] * inv1);
    }
}

// ============================================================================
// Launch
// ============================================================================
extern "C" void kernel_launch(void* const* d_in, const int* in_sizes, int n_in,
                              void* d_out, int out_size) {
    const float* x     = (const float*)d_in[0];
    const float* W_qkv = (const float*)d_in[1];
    const float* b_qkv = (const float*)d_in[2];
    const float* W_out = (const float*)d_in[3];
    const float* b_out = (const float*)d_in[4];
    float* out = (float*)d_out;

    float* attn_ptr;
    cudaGetSymbolAddress((void**)&attn_ptr, g_attn);
    __nv_bfloat16 *xh, *xl, *qkvh, *qkvl, *wq_hi, *wq_lo, *wo_hi, *wo_lo;
    cudaGetSymbolAddress((void**)&xh, g_xh);
    cudaGetSymbolAddress((void**)&xl, g_xl);
    cudaGetSymbolAddress((void**)&qkvh, g_qkvh);
    cudaGetSymbolAddress((void**)&qkvl, g_qkvl);
    cudaGetSymbolAddress((void**)&wq_hi, g_wq_hi);
    cudaGetSymbolAddress((void**)&wq_lo, g_wq_lo);
    cudaGetSymbolAddress((void**)&wo_hi, g_wo_hi);
    cudaGetSymbolAddress((void**)&wo_lo, g_wo_lo);

    cudaFuncSetAttribute(tc_gemm_qkv, cudaFuncAttributeMaxDynamicSharedMemorySize, SM_QKV_TOTAL);
    cudaFuncSetAttribute(tc_gemm_bias, cudaFuncAttributeMaxDynamicSharedMemorySize, SM_GEMM_TOTAL);
    cudaFuncSetAttribute(attn_mma_kernel, cudaFuncAttributeMaxDynamicSharedMemorySize, ATT_SMEM);

    // 0) prep: fused weight transpose+split, x split
    wtrans_split2_kernel<<<dim3(E3 / 32, EMBED / 32, 2), 256>>>(
        W_qkv, wq_hi, wq_lo, W_out, wo_hi, wo_lo);
    fsplit_kernel<<<(M_TOTAL * EMBED / 4) / 256, 256>>>(x, xh, xl);

    // 1) QKV projection (2 CTAs/SM, 192 thr) -> pre-split bf16, Q scaled 0.125
    tc_gemm_qkv<<<dim3(E3 / QBN, M_TOTAL / QBM), 192, SM_QKV_TOTAL>>>(
        xh, xl, wq_hi, wq_lo, b_qkv, qkvh, qkvl, M_TOTAL, E3, EMBED, EMBED);

    // 2) Attention (2 CTAs/SM) -> fp32
    dim3 g2(S_LEN / 128, HEADS, BATCH);
    attn_mma_kernel<<<g2, 256, ATT_SMEM>>>(qkvh, qkvl, attn_ptr);

    // 3) Output projection (banked r14 kernel) -> fp32 final output
    tc_gemm_bias<<<dim3(EMBED / BN, M_TOTAL / BM), 256, SM_GEMM_TOTAL>>>(
        attn_ptr, wo_hi, wo_lo, b_out, out, M_TOTAL, EMBED, EMBED);
}

// round 16
// speedup vs baseline: 1.5137x; 1.0070x over previous
#include <cuda_runtime.h>
#include <cuda_bf16.h>
#include <cstdint>

// ============================================================================
// Problem constants
// ============================================================================
#define S_LEN   2048
#define EMBED   1024
#define E3      3072
#define HEADS   16
#define HDIM    64
#define BATCH   4
#define M_TOTAL (BATCH * S_LEN) /* 8192 */
#define N_PAD   1056            /* EMBED padded to multiple of 96 */

// Scratch (allocation-free contract; device globals are zero-initialized)
__device__ __align__(16) __nv_bfloat16 g_xh[(size_t)M_TOTAL * EMBED];
__device__ __align__(16) __nv_bfloat16 g_xl[(size_t)M_TOTAL * EMBED];
__device__ __align__(16) __nv_bfloat16 g_qkvh[(size_t)M_TOTAL * E3];
__device__ __align__(16) __nv_bfloat16 g_qkvl[(size_t)M_TOTAL * E3];
__device__ __align__(16) __nv_bfloat16 g_attnh[(size_t)M_TOTAL * EMBED];
__device__ __align__(16) __nv_bfloat16 g_attnl[(size_t)M_TOTAL * EMBED];
__device__ __align__(16) __nv_bfloat16 g_wq_hi[(size_t)E3 * EMBED];
__device__ __align__(16) __nv_bfloat16 g_wq_lo[(size_t)E3 * EMBED];
__device__ __align__(16) __nv_bfloat16 g_wo_hi[(size_t)N_PAD * EMBED]; // rows >=1024 stay zero
__device__ __align__(16) __nv_bfloat16 g_wo_lo[(size_t)N_PAD * EMBED];

// ============================================================================
// Helpers
// ============================================================================
__device__ __forceinline__ uint32_t smem_to_u32(const void* smem_ptr) {
    uint32_t addr;
    asm("{ .reg .u64 tmp; cvta.to.shared.u64 tmp, %1; cvt.u32.u64 %0, tmp; }"
        : "=r"(addr) : "l"(smem_ptr));
    return addr;
}

__device__ __forceinline__ void ldsm4(uint32_t addr, uint32_t r[4]) {
    asm volatile("ldmatrix.sync.aligned.m8n8.x4.shared.b16 {%0,%1,%2,%3}, [%4];"
                 : "=r"(r[0]), "=r"(r[1]), "=r"(r[2]), "=r"(r[3]) : "r"(addr));
}

__device__ __forceinline__ void ldsm4t(uint32_t addr, uint32_t r[4]) {
    asm volatile("ldmatrix.sync.aligned.m8n8.x4.trans.shared.b16 {%0,%1,%2,%3}, [%4];"
                 : "=r"(r[0]), "=r"(r[1]), "=r"(r[2]), "=r"(r[3]) : "r"(addr));
}

__device__ __forceinline__ void mma16816(float c[4], const uint32_t a[4],
                                         uint32_t b0, uint32_t b1) {
    asm volatile(
        "mma.sync.aligned.m16n8k16.row.col.f32.bf16.bf16.f32 "
        "{%0,%1,%2,%3}, {%4,%5,%6,%7}, {%8,%9}, {%0,%1,%2,%3};"
        : "+f"(c[0]), "+f"(c[1]), "+f"(c[2]), "+f"(c[3])
        : "r"(a[0]), "r"(a[1]), "r"(a[2]), "r"(a[3]), "r"(b0), "r"(b1));
}

__device__ __forceinline__ void cp_async16(uint32_t saddr, const void* gptr) {
    asm volatile("cp.async.cg.shared.global [%0], [%1], 16;"
                 :: "r"(saddr), "l"(gptr) : "memory");
}
#define CP_COMMIT() asm volatile("cp.async.commit_group;" ::: "memory")
#define CP_WAIT(n)  asm volatile("cp.async.wait_group %0;" :: "n"(n) : "memory")

__device__ __forceinline__ void split_bf16(float v, __nv_bfloat16& h, __nv_bfloat16& l) {
    h = __float2bfloat16(v);
    l = __float2bfloat16(v - __bfloat162float(h));
}

// pack (x,y) -> bf16x2 hi-word, residual pair -> lo-word
__device__ __forceinline__ void pack_split(float x, float y, uint32_t& hp, uint32_t& lp) {
    asm("cvt.rn.bf16x2.f32 %0, %1, %2;" : "=r"(hp) : "f"(y), "f"(x));
    const float hx = __uint_as_float(hp << 16);
    const float hy = __uint_as_float(hp & 0xffff0000u);
    const float rx = x - hx, ry = y - hy;
    asm("cvt.rn.bf16x2.f32 %0, %1, %2;" : "=r"(lp) : "f"(ry), "f"(rx));
}

// ============================================================================
// Prep (fused): transpose W[K,N] -> Wt[N,K], split fp32 into bf16 hi + lo.
// blockIdx.z = 0 -> W_qkv (N=3072), 1 -> W_out (N=1024, padded buffer).
// ============================================================================
__global__ __launch_bounds__(256)
void wtrans_split2_kernel(const float* __restrict__ W0, __nv_bfloat16* __restrict__ Th0,
                          __nv_bfloat16* __restrict__ Tl0,
                          const float* __restrict__ W1, __nv_bfloat16* __restrict__ Th1,
                          __nv_bfloat16* __restrict__ Tl1) {
    const int z = blockIdx.z;
    const int N = z ? EMBED : E3;
    const int n0 = blockIdx.x * 32, k0 = blockIdx.y * 32;
    if (n0 >= N) return;
    const float* W = z ? W1 : W0;
    __nv_bfloat16* Th = z ? Th1 : Th0;
    __nv_bfloat16* Tl = z ? Tl1 : Tl0;
    const int K = EMBED;

    __shared__ float t[32][33];
    const int tid = threadIdx.x;
    const int c = tid & 31, r = tid >> 5;
#pragma unroll
    for (int i = 0; i < 4; i++)
        t[r + i * 8][c] = W[(size_t)(k0 + r + i * 8) * N + n0 + c];
    __syncthreads();
    const int n  = tid >> 3;
    const int kq = (tid & 7) * 4;
    __nv_bfloat16 h[4], l[4];
#pragma unroll
    for (int j = 0; j < 4; j++) split_bf16(t[kq + j][n], h[j], l[j]);
    const size_t o = (size_t)(n0 + n) * K + k0 + kq;
    *(__nv_bfloat162*)&Th[o]     = __halves2bfloat162(h[0], h[1]);
    *(__nv_bfloat162*)&Th[o + 2] = __halves2bfloat162(h[2], h[3]);
    *(__nv_bfloat162*)&Tl[o]     = __halves2bfloat162(l[0], l[1]);
    *(__nv_bfloat162*)&Tl[o + 2] = __halves2bfloat162(l[2], l[3]);
}

// ============================================================================
// Prep 2: elementwise fp32 -> bf16 hi/lo split (for x)
// ============================================================================
__global__ __launch_bounds__(256)
void fsplit_kernel(const float* __restrict__ X, __nv_bfloat16* __restrict__ Xh,
                   __nv_bfloat16* __restrict__ Xl) {
    const size_t idx = (size_t)blockIdx.x * 256 + threadIdx.x;
    const float4 v = ((const float4*)X)[idx];
    uint32_t h0, l0, h1, l1;
    pack_split(v.x, v.y, h0, l0);
    pack_split(v.z, v.w, h1, l1);
    ((uint2*)Xh)[idx] = make_uint2(h0, h1);
    ((uint2*)Xl)[idx] = make_uint2(l0, l1);
}

// ============================================================================
// GEMM, 2-CTA/SM (round-15 winner): CTA 128(M) x 96(N), 192 threads
// (6 warps, 2x3), warp tile 64x32, BK=64, bf16 cp.async 2-stage producer.
// Stage 56KB, smem 112KB -> 2 CTAs/SM, 168-reg budget.
// Output: fp32 (Cf) or pre-split bf16 (Ch/Cl). Epilogue guarded gcol < N
// (supports padded B with N_B >= grid.x*96 rows). Cols < scale_cols *0.125.
// ============================================================================
#define QBM 128
#define QBN 96
#define QA_TILE 16384
#define QB_TILE 12288
#define QOFF_AH 0
#define QOFF_AL QA_TILE
#define QOFF_BH (2 * QA_TILE)
#define QOFF_BL (2 * QA_TILE + QB_TILE)
#define QSTAGE_SZ  (2 * QA_TILE + 2 * QB_TILE)  /* 57344 */
#define SM_QKV_TOTAL (2 * QSTAGE_SZ)            /* 114688 */

__global__ __launch_bounds__(192, 2)
void tc_gemm_192(const __nv_bfloat16* __restrict__ Ah, const __nv_bfloat16* __restrict__ Al,
                 const __nv_bfloat16* __restrict__ Bth, const __nv_bfloat16* __restrict__ Btl,
                 const float* __restrict__ bias,
                 float* __restrict__ Cf,
                 __nv_bfloat16* __restrict__ Ch, __nv_bfloat16* __restrict__ Cl,
                 int M, int N, int K, int scale_cols) {
    extern __shared__ char smem[];
    const uint32_t sb = smem_to_u32(smem);
    const int tid  = threadIdx.x;
    const int wid  = tid >> 5;
    const int lane = tid & 31;
    const int row0 = blockIdx.y * QBM;
    const int col0 = blockIdx.x * QBN;
    const int nchunks = K / 64;

    auto issue = [&](int c) {
        const uint32_t st = sb + (uint32_t)(c & 1) * QSTAGE_SZ;
        const int k0 = c * 64;
#pragma unroll
        for (int it = 0; it < 11; it++) {
            const int idx = tid + it * 192;
            if (it == 10 && idx >= 2048) break;
            const int row2 = idx >> 3;
            const int ch   = idx & 7;
            const int r    = row2 & 127;
            const __nv_bfloat16* g = (row2 < 128)
                ? (Ah + (size_t)(row0 + r) * K) : (Al + (size_t)(row0 + r) * K);
            const uint32_t soff = (uint32_t)((row2 < 128 ? QOFF_AH : QOFF_AL) + r * 128)
                + (((uint32_t)(ch * 16)) ^ (((uint32_t)r & 7) << 4));
            cp_async16(st + soff, g + k0 + ch * 8);
        }
#pragma unroll
        for (int it = 0; it < 8; it++) {
            const int idx = tid + it * 192;
            const int row2 = idx >> 3;
            const int ch   = idx & 7;
            const int r    = (row2 < 96) ? row2 : row2 - 96;
            const __nv_bfloat16* g = (row2 < 96)
                ? (Bth + (size_t)(col0 + r) * K) : (Btl + (size_t)(col0 + r) * K);
            const uint32_t soff = (uint32_t)((row2 < 96 ? QOFF_BH : QOFF_BL) + r * 128)
                + (((uint32_t)(ch * 16)) ^ (((uint32_t)r & 7) << 4));
            cp_async16(st + soff, g + k0 + ch * 8);
        }
        CP_COMMIT();
    };

    const int wm = (wid / 3) * 64;
    const int wn = (wid % 3) * 32;
    const int a_r    = lane & 15;
    const int a_half = lane >> 4;
    const int b_nr   = (lane & 7) | ((lane >> 4) << 3);
    const int b_kh   = (lane >> 3) & 1;

    uint32_t a_rowoff[4], a_xor[4], b_rowoff[2], b_xor[2];
#pragma unroll
    for (int i = 0; i < 4; i++) {
        const int r = wm + i * 16 + a_r;
        a_rowoff[i] = (uint32_t)(r * 128);
        a_xor[i]    = (uint32_t)((r & 7) << 4);
    }
#pragma unroll
    for (int jp = 0; jp < 2; jp++) {
        const int r = wn + jp * 16 + b_nr;
        b_rowoff[jp] = (uint32_t)(r * 128);
        b_xor[jp]    = (uint32_t)((r & 7) << 4);
    }
    const uint32_t a_kbb = (uint32_t)(a_half * 16);
    const uint32_t b_kbb = (uint32_t)(b_kh * 16);

    float acc[4][4][4];
#pragma unroll
    for (int i = 0; i < 4; i++)
#pragma unroll
        for (int j = 0; j < 4; j++)
#pragma unroll
            for (int q = 0; q < 4; q++) acc[i][j][q] = 0.f;

    issue(0);
    issue(1);

    for (int c = 0; c < nchunks; c++) {
        if (c + 1 < nchunks) { CP_WAIT(1); } else { CP_WAIT(0); }
        __syncthreads();

        const uint32_t st = sb + (uint32_t)(c & 1) * QSTAGE_SZ;
#pragma unroll
        for (int ks = 0; ks < 4; ks++) {
            const uint32_t kbA = (uint32_t)(ks * 32) + a_kbb;
            const uint32_t kbB = (uint32_t)(ks * 32) + b_kbb;
            uint32_t ah[4][4], al[4][4], bh[2][4], bl[2][4];
#pragma unroll
            for (int i = 0; i < 4; i++) {
                ldsm4(st + QOFF_AH + a_rowoff[i] + (kbA ^ a_xor[i]), ah[i]);
                ldsm4(st + QOFF_AL + a_rowoff[i] + (kbA ^ a_xor[i]), al[i]);
            }
#pragma unroll
            for (int jp = 0; jp < 2; jp++) {
                ldsm4(st + QOFF_BH + b_rowoff[jp] + (kbB ^ b_xor[jp]), bh[jp]);
                ldsm4(st + QOFF_BL + b_rowoff[jp] + (kbB ^ b_xor[jp]), bl[jp]);
            }
#pragma unroll
            for (int i = 0; i < 4; i++)
#pragma unroll
                for (int j = 0; j < 4; j++)
                    mma16816(acc[i][j], ah[i], bh[j >> 1][(j & 1) * 2], bh[j >> 1][(j & 1) * 2 + 1]);
#pragma unroll
            for (int i = 0; i < 4; i++)
#pragma unroll
                for (int j = 0; j < 4; j++)
                    mma16816(acc[i][j], ah[i], bl[j >> 1][(j & 1) * 2], bl[j >> 1][(j & 1) * 2 + 1]);
#pragma unroll
            for (int i = 0; i < 4; i++)
#pragma unroll
                for (int j = 0; j < 4; j++)
                    mma16816(acc[i][j], al[i], bh[j >> 1][(j & 1) * 2], bh[j >> 1][(j & 1) * 2 + 1]);
        }
        __syncthreads();
        if (c + 2 < nchunks) issue(c + 2);
    }

    // ---- epilogue (guarded for padded N) ----
    const int cr  = lane >> 2;
    const int cc2 = (lane & 3) * 2;
#pragma unroll
    for (int i = 0; i < 4; i++) {
#pragma unroll
        for (int j = 0; j < 4; j++) {
            const int gcol = col0 + wn + j * 8 + cc2;
            if (gcol >= N) continue;
            const int r0 = row0 + wm + i * 16 + cr;
            const float b0 = __ldg(&bias[gcol]), b1 = __ldg(&bias[gcol + 1]);
            float v0 = acc[i][j][0] + b0;
            float v1 = acc[i][j][1] + b1;
            float v2 = acc[i][j][2] + b0;
            float v3 = acc[i][j][3] + b1;
            if (gcol < scale_cols) { v0 *= 0.125f; v1 *= 0.125f; v2 *= 0.125f; v3 *= 0.125f; }
            if (Cf) {
                *(float2*)&Cf[(size_t)r0 * N + gcol]       = make_float2(v0, v1);
                *(float2*)&Cf[(size_t)(r0 + 8) * N + gcol] = make_float2(v2, v3);
            } else {
                uint32_t hp, lp;
                pack_split(v0, v1, hp, lp);
                *(uint32_t*)&Ch[(size_t)r0 * N + gcol] = hp;
                *(uint32_t*)&Cl[(size_t)r0 * N + gcol] = lp;
                pack_split(v2, v3, hp, lp);
                *(uint32_t*)&Ch[(size_t)(r0 + 8) * N + gcol] = hp;
                *(uint32_t*)&Cl[(size_t)(r0 + 8) * N + gcol] = lp;
            }
        }
    }
}

// ============================================================================
// HMMA flash attention (round-10/15 winner body; pre-split bf16 output,
// the r11/r12-verified epilogue). CTA = 128 q-rows x (head, batch),
// 8 warps, K/V tiles 64 rows, double-buffered, 2 CTAs/SM.
// ============================================================================
#define ATT_STAGE 32768
#define ATT_SMEM  (32768 + 2 * ATT_STAGE)  /* 98304 */
#define KT_ROWS   64

__global__ __launch_bounds__(256, 2)
void attn_mma_kernel(const __nv_bfloat16* __restrict__ QKVh,
                     const __nv_bfloat16* __restrict__ QKVl,
                     __nv_bfloat16* __restrict__ Oh,
                     __nv_bfloat16* __restrict__ Ol) {
    extern __shared__ char smem[];
    const uint32_t sb = smem_to_u32(smem);
    const int tid = threadIdx.x, wid = tid >> 5, lane = tid & 31;
    const int qt = blockIdx.x, h = blockIdx.y, b = blockIdx.z;
    const size_t rowbase = (size_t)b * S_LEN;
    const int hcol = h * HDIM;

    const uint32_t sQH = sb, sQL = sb + 16384;

    {
        const int p_r  = tid >> 1;
        const int p_cb = (tid & 1) * 64;
        const size_t grow = (rowbase + qt * 128 + p_r) * E3 + hcol;
#pragma unroll
        for (int i = 0; i < 4; i++) {
            const uint32_t bc  = (uint32_t)(p_cb + i * 16);
            const uint32_t off = (uint32_t)(p_r * 128) + (bc ^ (((uint32_t)p_r & 7) << 4));
            cp_async16(sQH + off, QKVh + grow + (bc >> 1));
            cp_async16(sQL + off, QKVl + grow + (bc >> 1));
        }
    }
    const int q_r  = tid >> 2;
    const int q_cb = (tid & 3) * 32;
    auto issue_kv = [&](int kt) {
        const uint32_t st = sb + 32768 + (uint32_t)(kt & 1) * ATT_STAGE;
        const size_t growK = (rowbase + kt * KT_ROWS + q_r) * E3 + (EMBED + hcol);
        const size_t growV = growK + EMBED;
#pragma unroll
        for (int i = 0; i < 2; i++) {
            const uint32_t bc  = (uint32_t)(q_cb + i * 16);
            const uint32_t off = (uint32_t)(q_r * 128) + (bc ^ (((uint32_t)q_r & 7) << 4));
            cp_async16(st + off,         QKVh + growK + (bc >> 1));
            cp_async16(st + 8192 + off,  QKVl + growK + (bc >> 1));
            cp_async16(st + 16384 + off, QKVh + growV + (bc >> 1));
            cp_async16(st + 24576 + off, QKVl + growV + (bc >> 1));
        }
    };
    issue_kv(0);
    CP_COMMIT();

    const int wm = wid * 16;
    const int a_row = wm + (lane & 15);
    const uint32_t a_rowoff = (uint32_t)(a_row * 128);
    const uint32_t a_xor    = ((uint32_t)a_row & 7) << 4;
    const uint32_t a_kbb    = (uint32_t)((lane >> 4) * 16);
    const int b_nr = (lane & 7) | ((lane >> 4) << 3);
    const uint32_t b_kbb = (uint32_t)(((lane >> 3) & 1) * 16);
    const uint32_t b_xor = ((uint32_t)lane & 7) << 4;
    const int v_r = ((lane >> 3) & 1) * 8 + (lane & 7);
    const uint32_t v_cbb = (uint32_t)((lane >> 4) * 16);
    const uint32_t v_xor = ((uint32_t)lane & 7) << 4;

    float m0 = -1e30f, m1 = -1e30f, l0 = 0.f, l1 = 0.f;
    float o[8][4];
#pragma unroll
    for (int j = 0; j < 8; j++)
#pragma unroll
        for (int q = 0; q < 4; q++) o[j][q] = 0.f;

    for (int kt = 0; kt < S_LEN / KT_ROWS; kt++) {
        const uint32_t st = sb + 32768 + (uint32_t)(kt & 1) * ATT_STAGE;
        if (kt + 1 < S_LEN / KT_ROWS) {
            issue_kv(kt + 1);
            CP_COMMIT();
            asm volatile("cp.async.wait_group 1;" ::: "memory");
        } else {
            asm volatile("cp.async.wait_group 0;" ::: "memory");
        }
        __syncthreads();

        float s[8][4];
#pragma unroll
        for (int j = 0; j < 8; j++)
#pragma unroll
            for (int q = 0; q < 4; q++) s[j][q] = 0.f;

#pragma unroll
        for (int ks = 0; ks < 4; ks++) {
            const uint32_t akb = (uint32_t)(ks * 32) + a_kbb;
            uint32_t qh[4], ql[4];
            ldsm4(sQH + a_rowoff + (akb ^ a_xor), qh);
            ldsm4(sQL + a_rowoff + (akb ^ a_xor), ql);
            const uint32_t kcb = ((uint32_t)(ks * 32) + b_kbb) ^ b_xor;
#pragma unroll
            for (int jp = 0; jp < 4; jp++) {
                const uint32_t roff = (uint32_t)((jp * 16 + b_nr) * 128);
                uint32_t kh[4], kl[4];
                ldsm4(st + roff + kcb, kh);
                ldsm4(st + 8192 + roff + kcb, kl);
                mma16816(s[2 * jp],     qh, kh[0], kh[1]);
                mma16816(s[2 * jp + 1], qh, kh[2], kh[3]);
                mma16816(s[2 * jp],     qh, kl[0], kl[1]);
                mma16816(s[2 * jp + 1], qh, kl[2], kl[3]);
                mma16816(s[2 * jp],     ql, kh[0], kh[1]);
                mma16816(s[2 * jp + 1], ql, kh[2], kh[3]);
            }
        }

        float mx0 = -1e30f, mx1 = -1e30f;
#pragma unroll
        for (int j = 0; j < 8; j++) {
            mx0 = fmaxf(mx0, fmaxf(s[j][0], s[j][1]));
            mx1 = fmaxf(mx1, fmaxf(s[j][2], s[j][3]));
        }
        mx0 = fmaxf(mx0, __shfl_xor_sync(0xffffffffu, mx0, 1));
        mx0 = fmaxf(mx0, __shfl_xor_sync(0xffffffffu, mx0, 2));
        mx1 = fmaxf(mx1, __shfl_xor_sync(0xffffffffu, mx1, 1));
        mx1 = fmaxf(mx1, __shfl_xor_sync(0xffffffffu, mx1, 2));
        const float mn0 = fmaxf(m0, mx0), mn1 = fmaxf(m1, mx1);
        const float al0 = __expf(m0 - mn0), al1 = __expf(m1 - mn1);
#pragma unroll
        for (int j = 0; j < 8; j++) {
            o[j][0] *= al0; o[j][1] *= al0;
            o[j][2] *= al1; o[j][3] *= al1;
        }
        float sum0 = 0.f, sum1 = 0.f;
#pragma unroll
        for (int j = 0; j < 8; j++) {
            s[j][0] = __expf(s[j][0] - mn0);
            s[j][1] = __expf(s[j][1] - mn0);
            s[j][2] = __expf(s[j][2] - mn1);
            s[j][3] = __expf(s[j][3] - mn1);
            sum0 += s[j][0] + s[j][1];
            sum1 += s[j][2] + s[j][3];
        }
        sum0 += __shfl_xor_sync(0xffffffffu, sum0, 1);
        sum0 += __shfl_xor_sync(0xffffffffu, sum0, 2);
        sum1 += __shfl_xor_sync(0xffffffffu, sum1, 1);
        sum1 += __shfl_xor_sync(0xffffffffu, sum1, 2);
        l0 = l0 * al0 + sum0;
        l1 = l1 * al1 + sum1;
        m0 = mn0; m1 = mn1;

#pragma unroll
        for (int kk = 0; kk < 4; kk++) {
            uint32_t aph[4], apl[4];
            pack_split(s[2 * kk][0],     s[2 * kk][1],     aph[0], apl[0]);
            pack_split(s[2 * kk][2],     s[2 * kk][3],     aph[1], apl[1]);
            pack_split(s[2 * kk + 1][0], s[2 * kk + 1][1], aph[2], apl[2]);
            pack_split(s[2 * kk + 1][2], s[2 * kk + 1][3], aph[3], apl[3]);
            const uint32_t vroff = (uint32_t)((kk * 16 + v_r) * 128);
#pragma unroll
            for (int jn = 0; jn < 4; jn++) {
                const uint32_t vcb = ((uint32_t)(jn * 32) + v_cbb) ^ v_xor;
                uint32_t vh[4], vl[4];
                ldsm4t(st + 16384 + vroff + vcb, vh);
                ldsm4t(st + 24576 + vroff + vcb, vl);
                mma16816(o[2 * jn],     aph, vh[0], vh[1]);
                mma16816(o[2 * jn + 1], aph, vh[2], vh[3]);
                mma16816(o[2 * jn],     aph, vl[0], vl[1]);
                mma16816(o[2 * jn + 1], aph, vl[2], vl[3]);
                mma16816(o[2 * jn],     apl, vh[0], vh[1]);
                mma16816(o[2 * jn + 1], apl, vh[2], vh[3]);
            }
        }
        __syncthreads();
    }

    // === epilogue: normalize, pre-split bf16, write ===
    const int gr  = lane >> 2;
    const int cc2 = (lane & 3) * 2;
    const float inv0 = 1.f / l0, inv1 = 1.f / l1;
    const size_t r0 = rowbase + (size_t)(qt * 128 + wm + gr);
#pragma unroll
    for (int j = 0; j < 8; j++) {
        const int col = hcol + j * 8 + cc2;
        uint32_t hp, lp;
        pack_split(o[j][0] * inv0, o[j][1] * inv0, hp, lp);
        *(uint32_t*)&Oh[r0 * EMBED + col] = hp;
        *(uint32_t*)&Ol[r0 * EMBED + col] = lp;
        pack_split(o[j][2] * inv1, o[j][3] * inv1, hp, lp);
        *(uint32_t*)&Oh[(r0 + 8) * EMBED + col] = hp;
        *(uint32_t*)&Ol[(r0 + 8) * EMBED + col] = lp;
    }
}

// ============================================================================
// Launch
// ============================================================================
extern "C" void kernel_launch(void* const* d_in, const int* in_sizes, int n_in,
                              void* d_out, int out_size) {
    const float* x     = (const float*)d_in[0];
    const float* W_qkv = (const float*)d_in[1];
    const float* b_qkv = (const float*)d_in[2];
    const float* W_out = (const float*)d_in[3];
    const float* b_out = (const float*)d_in[4];
    float* out = (float*)d_out;

    __nv_bfloat16 *xh, *xl, *qkvh, *qkvl, *attnh, *attnl;
    __nv_bfloat16 *wq_hi, *wq_lo, *wo_hi, *wo_lo;
    cudaGetSymbolAddress((void**)&xh, g_xh);
    cudaGetSymbolAddress((void**)&xl, g_xl);
    cudaGetSymbolAddress((void**)&qkvh, g_qkvh);
    cudaGetSymbolAddress((void**)&qkvl, g_qkvl);
    cudaGetSymbolAddress((void**)&attnh, g_attnh);
    cudaGetSymbolAddress((void**)&attnl, g_attnl);
    cudaGetSymbolAddress((void**)&wq_hi, g_wq_hi);
    cudaGetSymbolAddress((void**)&wq_lo, g_wq_lo);
    cudaGetSymbolAddress((void**)&wo_hi, g_wo_hi);
    cudaGetSymbolAddress((void**)&wo_lo, g_wo_lo);

    cudaFuncSetAttribute(tc_gemm_192, cudaFuncAttributeMaxDynamicSharedMemorySize, SM_QKV_TOTAL);
    cudaFuncSetAttribute(attn_mma_kernel, cudaFuncAttributeMaxDynamicSharedMemorySize, ATT_SMEM);

    // 0) prep: fused weight transpose+split (wo into padded buffer), x split
    wtrans_split2_kernel<<<dim3(E3 / 32, EMBED / 32, 2), 256>>>(
        W_qkv, wq_hi, wq_lo, W_out, wo_hi, wo_lo);
    fsplit_kernel<<<(M_TOTAL * EMBED / 4) / 256, 256>>>(x, xh, xl);

    // 1) QKV projection (2 CTAs/SM) -> pre-split bf16, Q scaled 0.125
    tc_gemm_192<<<dim3(E3 / QBN, M_TOTAL / QBM), 192, SM_QKV_TOTAL>>>(
        xh, xl, wq_hi, wq_lo, b_qkv, nullptr, qkvh, qkvl, M_TOTAL, E3, EMBED, EMBED);

    // 2) Attention (2 CTAs/SM) -> pre-split bf16
    dim3 g2(S_LEN / 128, HEADS, BATCH);
    attn_mma_kernel<<<g2, 256, ATT_SMEM>>>(qkvh, qkvl, attnh, attnl);

    // 3) Output projection (2 CTAs/SM, padded N=1056) -> fp32 final output
    tc_gemm_192<<<dim3(N_PAD / QBN, M_TOTAL / QBM), 192, SM_QKV_TOTAL>>>(
        attnh, attnl, wo_hi, wo_lo, b_out, out, nullptr, nullptr, M_TOTAL, EMBED, EMBED, 0);
}

// round 17
// speedup vs baseline: 1.5234x; 1.0064x over previous
#include <cuda_runtime.h>
#include <cuda_bf16.h>
#include <cstdint>

// ============================================================================
// Problem constants
// ============================================================================
#define S_LEN   2048
#define EMBED   1024
#define E3      3072
#define HEADS   16
#define HDIM    64
#define BATCH   4
#define M_TOTAL (BATCH * S_LEN) /* 8192 */
#define N_PAD   1056            /* EMBED padded to multiple of 96 */
// Q pre-scale: (1/sqrt(64)) * log2(e), folded so softmax runs in base-2
#define Q_SCALE 0.1803368801111204f

// Scratch (allocation-free contract; device globals are zero-initialized)
__device__ __align__(16) __nv_bfloat16 g_xh[(size_t)M_TOTAL * EMBED];
__device__ __align__(16) __nv_bfloat16 g_xl[(size_t)M_TOTAL * EMBED];
__device__ __align__(16) __nv_bfloat16 g_qkvh[(size_t)M_TOTAL * E3];
__device__ __align__(16) __nv_bfloat16 g_qkvl[(size_t)M_TOTAL * E3];
__device__ __align__(16) __nv_bfloat16 g_attnh[(size_t)M_TOTAL * EMBED];
__device__ __align__(16) __nv_bfloat16 g_attnl[(size_t)M_TOTAL * EMBED];
__device__ __align__(16) __nv_bfloat16 g_wq_hi[(size_t)E3 * EMBED];
__device__ __align__(16) __nv_bfloat16 g_wq_lo[(size_t)E3 * EMBED];
__device__ __align__(16) __nv_bfloat16 g_wo_hi[(size_t)N_PAD * EMBED]; // rows >=1024 stay zero
__device__ __align__(16) __nv_bfloat16 g_wo_lo[(size_t)N_PAD * EMBED];

// ============================================================================
// Helpers
// ============================================================================
__device__ __forceinline__ uint32_t smem_to_u32(const void* smem_ptr) {
    uint32_t addr;
    asm("{ .reg .u64 tmp; cvta.to.shared.u64 tmp, %1; cvt.u32.u64 %0, tmp; }"
        : "=r"(addr) : "l"(smem_ptr));
    return addr;
}

__device__ __forceinline__ void ldsm4(uint32_t addr, uint32_t r[4]) {
    asm volatile("ldmatrix.sync.aligned.m8n8.x4.shared.b16 {%0,%1,%2,%3}, [%4];"
                 : "=r"(r[0]), "=r"(r[1]), "=r"(r[2]), "=r"(r[3]) : "r"(addr));
}

__device__ __forceinline__ void ldsm4t(uint32_t addr, uint32_t r[4]) {
    asm volatile("ldmatrix.sync.aligned.m8n8.x4.trans.shared.b16 {%0,%1,%2,%3}, [%4];"
                 : "=r"(r[0]), "=r"(r[1]), "=r"(r[2]), "=r"(r[3]) : "r"(addr));
}

__device__ __forceinline__ void mma16816(float c[4], const uint32_t a[4],
                                         uint32_t b0, uint32_t b1) {
    asm volatile(
        "mma.sync.aligned.m16n8k16.row.col.f32.bf16.bf16.f32 "
        "{%0,%1,%2,%3}, {%4,%5,%6,%7}, {%8,%9}, {%0,%1,%2,%3};"
        : "+f"(c[0]), "+f"(c[1]), "+f"(c[2]), "+f"(c[3])
        : "r"(a[0]), "r"(a[1]), "r"(a[2]), "r"(a[3]), "r"(b0), "r"(b1));
}

__device__ __forceinline__ void cp_async16(uint32_t saddr, const void* gptr) {
    asm volatile("cp.async.cg.shared.global [%0], [%1], 16;"
                 :: "r"(saddr), "l"(gptr) : "memory");
}
#define CP_COMMIT() asm volatile("cp.async.commit_group;" ::: "memory")
#define CP_WAIT(n)  asm volatile("cp.async.wait_group %0;" :: "n"(n) : "memory")

__device__ __forceinline__ void split_bf16(float v, __nv_bfloat16& h, __nv_bfloat16& l) {
    h = __float2bfloat16(v);
    l = __float2bfloat16(v - __bfloat162float(h));
}

// raw base-2 exponential (single MUFU.EX2, no pre-multiply)
__device__ __forceinline__ float ex2(float x) {
    float r;
    asm("ex2.approx.f32 %0, %1;" : "=f"(r) : "f"(x));
    return r;
}

// pack (x,y) -> bf16x2 hi-word, residual pair -> lo-word
__device__ __forceinline__ void pack_split(float x, float y, uint32_t& hp, uint32_t& lp) {
    asm("cvt.rn.bf16x2.f32 %0, %1, %2;" : "=r"(hp) : "f"(y), "f"(x));
    const float hx = __uint_as_float(hp << 16);
    const float hy = __uint_as_float(hp & 0xffff0000u);
    const float rx = x - hx, ry = y - hy;
    asm("cvt.rn.bf16x2.f32 %0, %1, %2;" : "=r"(lp) : "f"(ry), "f"(rx));
}

// ============================================================================
// Prep (fused): transpose W[K,N] -> Wt[N,K], split fp32 into bf16 hi + lo.
// blockIdx.z = 0 -> W_qkv (N=3072), 1 -> W_out (N=1024, padded buffer).
// ============================================================================
__global__ __launch_bounds__(256)
void wtrans_split2_kernel(const float* __restrict__ W0, __nv_bfloat16* __restrict__ Th0,
                          __nv_bfloat16* __restrict__ Tl0,
                          const float* __restrict__ W1, __nv_bfloat16* __restrict__ Th1,
                          __nv_bfloat16* __restrict__ Tl1) {
    const int z = blockIdx.z;
    const int N = z ? EMBED : E3;
    const int n0 = blockIdx.x * 32, k0 = blockIdx.y * 32;
    if (n0 >= N) return;
    const float* W = z ? W1 : W0;
    __nv_bfloat16* Th = z ? Th1 : Th0;
    __nv_bfloat16* Tl = z ? Tl1 : Tl0;
    const int K = EMBED;

    __shared__ float t[32][33];
    const int tid = threadIdx.x;
    const int c = tid & 31, r = tid >> 5;
#pragma unroll
    for (int i = 0; i < 4; i++)
        t[r + i * 8][c] = W[(size_t)(k0 + r + i * 8) * N + n0 + c];
    __syncthreads();
    const int n  = tid >> 3;
    const int kq = (tid & 7) * 4;
    __nv_bfloat16 h[4], l[4];
#pragma unroll
    for (int j = 0; j < 4; j++) split_bf16(t[kq + j][n], h[j], l[j]);
    const size_t o = (size_t)(n0 + n) * K + k0 + kq;
    *(__nv_bfloat162*)&Th[o]     = __halves2bfloat162(h[0], h[1]);
    *(__nv_bfloat162*)&Th[o + 2] = __halves2bfloat162(h[2], h[3]);
    *(__nv_bfloat162*)&Tl[o]     = __halves2bfloat162(l[0], l[1]);
    *(__nv_bfloat162*)&Tl[o + 2] = __halves2bfloat162(l[2], l[3]);
}

// ============================================================================
// Prep 2: elementwise fp32 -> bf16 hi/lo split (for x)
// ============================================================================
__global__ __launch_bounds__(256)
void fsplit_kernel(const float* __restrict__ X, __nv_bfloat16* __restrict__ Xh,
                   __nv_bfloat16* __restrict__ Xl) {
    const size_t idx = (size_t)blockIdx.x * 256 + threadIdx.x;
    const float4 v = ((const float4*)X)[idx];
    uint32_t h0, l0, h1, l1;
    pack_split(v.x, v.y, h0, l0);
    pack_split(v.z, v.w, h1, l1);
    ((uint2*)Xh)[idx] = make_uint2(h0, h1);
    ((uint2*)Xl)[idx] = make_uint2(l0, l1);
}

// ============================================================================
// GEMM, 2-CTA/SM (round-15/16 winner): CTA 128(M) x 96(N), 192 threads
// (6 warps, 2x3), warp tile 64x32, BK=64, bf16 cp.async 2-stage producer.
// Output: fp32 (Cf) or pre-split bf16 (Ch/Cl). Epilogue guarded gcol < N.
// Cols < scale_cols multiplied by qscale (Q pre-scale incl. log2e fold).
// ============================================================================
#define QBM 128
#define QBN 96
#define QA_TILE 16384
#define QB_TILE 12288
#define QOFF_AH 0
#define QOFF_AL QA_TILE
#define QOFF_BH (2 * QA_TILE)
#define QOFF_BL (2 * QA_TILE + QB_TILE)
#define QSTAGE_SZ  (2 * QA_TILE + 2 * QB_TILE)  /* 57344 */
#define SM_QKV_TOTAL (2 * QSTAGE_SZ)            /* 114688 */

__global__ __launch_bounds__(192, 2)
void tc_gemm_192(const __nv_bfloat16* __restrict__ Ah, const __nv_bfloat16* __restrict__ Al,
                 const __nv_bfloat16* __restrict__ Bth, const __nv_bfloat16* __restrict__ Btl,
                 const float* __restrict__ bias,
                 float* __restrict__ Cf,
                 __nv_bfloat16* __restrict__ Ch, __nv_bfloat16* __restrict__ Cl,
                 int M, int N, int K, int scale_cols, float qscale) {
    extern __shared__ char smem[];
    const uint32_t sb = smem_to_u32(smem);
    const int tid  = threadIdx.x;
    const int wid  = tid >> 5;
    const int lane = tid & 31;
    const int row0 = blockIdx.y * QBM;
    const int col0 = blockIdx.x * QBN;
    const int nchunks = K / 64;

    auto issue = [&](int c) {
        const uint32_t st = sb + (uint32_t)(c & 1) * QSTAGE_SZ;
        const int k0 = c * 64;
#pragma unroll
        for (int it = 0; it < 11; it++) {
            const int idx = tid + it * 192;
            if (it == 10 && idx >= 2048) break;
            const int row2 = idx >> 3;
            const int ch   = idx & 7;
            const int r    = row2 & 127;
            const __nv_bfloat16* g = (row2 < 128)
                ? (Ah + (size_t)(row0 + r) * K) : (Al + (size_t)(row0 + r) * K);
            const uint32_t soff = (uint32_t)((row2 < 128 ? QOFF_AH : QOFF_AL) + r * 128)
                + (((uint32_t)(ch * 16)) ^ (((uint32_t)r & 7) << 4));
            cp_async16(st + soff, g + k0 + ch * 8);
        }
#pragma unroll
        for (int it = 0; it < 8; it++) {
            const int idx = tid + it * 192;
            const int row2 = idx >> 3;
            const int ch   = idx & 7;
            const int r    = (row2 < 96) ? row2 : row2 - 96;
            const __nv_bfloat16* g = (row2 < 96)
                ? (Bth + (size_t)(col0 + r) * K) : (Btl + (size_t)(col0 + r) * K);
            const uint32_t soff = (uint32_t)((row2 < 96 ? QOFF_BH : QOFF_BL) + r * 128)
                + (((uint32_t)(ch * 16)) ^ (((uint32_t)r & 7) << 4));
            cp_async16(st + soff, g + k0 + ch * 8);
        }
        CP_COMMIT();
    };

    const int wm = (wid / 3) * 64;
    const int wn = (wid % 3) * 32;
    const int a_r    = lane & 15;
    const int a_half = lane >> 4;
    const int b_nr   = (lane & 7) | ((lane >> 4) << 3);
    const int b_kh   = (lane >> 3) & 1;

    uint32_t a_rowoff[4], a_xor[4], b_rowoff[2], b_xor[2];
#pragma unroll
    for (int i = 0; i < 4; i++) {
        const int r = wm + i * 16 + a_r;
        a_rowoff[i] = (uint32_t)(r * 128);
        a_xor[i]    = (uint32_t)((r & 7) << 4);
    }
#pragma unroll
    for (int jp = 0; jp < 2; jp++) {
        const int r = wn + jp * 16 + b_nr;
        b_rowoff[jp] = (uint32_t)(r * 128);
        b_xor[jp]    = (uint32_t)((r & 7) << 4);
    }
    const uint32_t a_kbb = (uint32_t)(a_half * 16);
    const uint32_t b_kbb = (uint32_t)(b_kh * 16);

    float acc[4][4][4];
#pragma unroll
    for (int i = 0; i < 4; i++)
#pragma unroll
        for (int j = 0; j < 4; j++)
#pragma unroll
            for (int q = 0; q < 4; q++) acc[i][j][q] = 0.f;

    issue(0);
    issue(1);

    for (int c = 0; c < nchunks; c++) {
        if (c + 1 < nchunks) { CP_WAIT(1); } else { CP_WAIT(0); }
        __syncthreads();

        const uint32_t st = sb + (uint32_t)(c & 1) * QSTAGE_SZ;
#pragma unroll
        for (int ks = 0; ks < 4; ks++) {
            const uint32_t kbA = (uint32_t)(ks * 32) + a_kbb;
            const uint32_t kbB = (uint32_t)(ks * 32) + b_kbb;
            uint32_t ah[4][4], al[4][4], bh[2][4], bl[2][4];
#pragma unroll
            for (int i = 0; i < 4; i++) {
                ldsm4(st + QOFF_AH + a_rowoff[i] + (kbA ^ a_xor[i]), ah[i]);
                ldsm4(st + QOFF_AL + a_rowoff[i] + (kbA ^ a_xor[i]), al[i]);
            }
#pragma unroll
            for (int jp = 0; jp < 2; jp++) {
                ldsm4(st + QOFF_BH + b_rowoff[jp] + (kbB ^ b_xor[jp]), bh[jp]);
                ldsm4(st + QOFF_BL + b_rowoff[jp] + (kbB ^ b_xor[jp]), bl[jp]);
            }
#pragma unroll
            for (int i = 0; i < 4; i++)
#pragma unroll
                for (int j = 0; j < 4; j++)
                    mma16816(acc[i][j], ah[i], bh[j >> 1][(j & 1) * 2], bh[j >> 1][(j & 1) * 2 + 1]);
#pragma unroll
            for (int i = 0; i < 4; i++)
#pragma unroll
                for (int j = 0; j < 4; j++)
                    mma16816(acc[i][j], ah[i], bl[j >> 1][(j & 1) * 2], bl[j >> 1][(j & 1) * 2 + 1]);
#pragma unroll
            for (int i = 0; i < 4; i++)
#pragma unroll
                for (int j = 0; j < 4; j++)
                    mma16816(acc[i][j], al[i], bh[j >> 1][(j & 1) * 2], bh[j >> 1][(j & 1) * 2 + 1]);
        }
        __syncthreads();
        if (c + 2 < nchunks) issue(c + 2);
    }

    // ---- epilogue (guarded for padded N) ----
    const int cr  = lane >> 2;
    const int cc2 = (lane & 3) * 2;
#pragma unroll
    for (int i = 0; i < 4; i++) {
#pragma unroll
        for (int j = 0; j < 4; j++) {
            const int gcol = col0 + wn + j * 8 + cc2;
            if (gcol >= N) continue;
            const int r0 = row0 + wm + i * 16 + cr;
            const float b0 = __ldg(&bias[gcol]), b1 = __ldg(&bias[gcol + 1]);
            float v0 = acc[i][j][0] + b0;
            float v1 = acc[i][j][1] + b1;
            float v2 = acc[i][j][2] + b0;
            float v3 = acc[i][j][3] + b1;
            if (gcol < scale_cols) { v0 *= qscale; v1 *= qscale; v2 *= qscale; v3 *= qscale; }
            if (Cf) {
                *(float2*)&Cf[(size_t)r0 * N + gcol]       = make_float2(v0, v1);
                *(float2*)&Cf[(size_t)(r0 + 8) * N + gcol] = make_float2(v2, v3);
            } else {
                uint32_t hp, lp;
                pack_split(v0, v1, hp, lp);
                *(uint32_t*)&Ch[(size_t)r0 * N + gcol] = hp;
                *(uint32_t*)&Cl[(size_t)r0 * N + gcol] = lp;
                pack_split(v2, v3, hp, lp);
                *(uint32_t*)&Ch[(size_t)(r0 + 8) * N + gcol] = hp;
                *(uint32_t*)&Cl[(size_t)(r0 + 8) * N + gcol] = lp;
            }
        }
    }
}

// ============================================================================
// HMMA flash attention (round-16 winner body; base-2 online softmax, ex2).
// CTA = 128 q-rows x (head, batch), 8 warps, K/V tiles 64 rows,
// double-buffered, 2 CTAs/SM. Q pre-scaled by 0.125*log2(e) upstream.
// ============================================================================
#define ATT_STAGE 32768
#define ATT_SMEM  (32768 + 2 * ATT_STAGE)  /* 98304 */
#define KT_ROWS   64

__global__ __launch_bounds__(256, 2)
void attn_mma_kernel(const __nv_bfloat16* __restrict__ QKVh,
                     const __nv_bfloat16* __restrict__ QKVl,
                     __nv_bfloat16* __restrict__ Oh,
                     __nv_bfloat16* __restrict__ Ol) {
    extern __shared__ char smem[];
    const uint32_t sb = smem_to_u32(smem);
    const int tid = threadIdx.x, wid = tid >> 5, lane = tid & 31;
    const int qt = blockIdx.x, h = blockIdx.y, b = blockIdx.z;
    const size_t rowbase = (size_t)b * S_LEN;
    const int hcol = h * HDIM;

    const uint32_t sQH = sb, sQL = sb + 16384;

    {
        const int p_r  = tid >> 1;
        const int p_cb = (tid & 1) * 64;
        const size_t grow = (rowbase + qt * 128 + p_r) * E3 + hcol;
#pragma unroll
        for (int i = 0; i < 4; i++) {
            const uint32_t bc  = (uint32_t)(p_cb + i * 16);
            const uint32_t off = (uint32_t)(p_r * 128) + (bc ^ (((uint32_t)p_r & 7) << 4));
            cp_async16(sQH + off, QKVh + grow + (bc >> 1));
            cp_async16(sQL + off, QKVl + grow + (bc >> 1));
        }
    }
    const int q_r  = tid >> 2;
    const int q_cb = (tid & 3) * 32;
    auto issue_kv = [&](int kt) {
        const uint32_t st = sb + 32768 + (uint32_t)(kt & 1) * ATT_STAGE;
        const size_t growK = (rowbase + kt * KT_ROWS + q_r) * E3 + (EMBED + hcol);
        const size_t growV = growK + EMBED;
#pragma unroll
        for (int i = 0; i < 2; i++) {
            const uint32_t bc  = (uint32_t)(q_cb + i * 16);
            const uint32_t off = (uint32_t)(q_r * 128) + (bc ^ (((uint32_t)q_r & 7) << 4));
            cp_async16(st + off,         QKVh + growK + (bc >> 1));
            cp_async16(st + 8192 + off,  QKVl + growK + (bc >> 1));
            cp_async16(st + 16384 + off, QKVh + growV + (bc >> 1));
            cp_async16(st + 24576 + off, QKVl + growV + (bc >> 1));
        }
    };
    issue_kv(0);
    CP_COMMIT();

    const int wm = wid * 16;
    const int a_row = wm + (lane & 15);
    const uint32_t a_rowoff = (uint32_t)(a_row * 128);
    const uint32_t a_xor    = ((uint32_t)a_row & 7) << 4;
    const uint32_t a_kbb    = (uint32_t)((lane >> 4) * 16);
    const int b_nr = (lane & 7) | ((lane >> 4) << 3);
    const uint32_t b_kbb = (uint32_t)(((lane >> 3) & 1) * 16);
    const uint32_t b_xor = ((uint32_t)lane & 7) << 4;
    const int v_r = ((lane >> 3) & 1) * 8 + (lane & 7);
    const uint32_t v_cbb = (uint32_t)((lane >> 4) * 16);
    const uint32_t v_xor = ((uint32_t)lane & 7) << 4;

    float m0 = -1e30f, m1 = -1e30f, l0 = 0.f, l1 = 0.f;
    float o[8][4];
#pragma unroll
    for (int j = 0; j < 8; j++)
#pragma unroll
        for (int q = 0; q < 4; q++) o[j][q] = 0.f;

    for (int kt = 0; kt < S_LEN / KT_ROWS; kt++) {
        const uint32_t st = sb + 32768 + (uint32_t)(kt & 1) * ATT_STAGE;
        if (kt + 1 < S_LEN / KT_ROWS) {
            issue_kv(kt + 1);
            CP_COMMIT();
            asm volatile("cp.async.wait_group 1;" ::: "memory");
        } else {
            asm volatile("cp.async.wait_group 0;" ::: "memory");
        }
        __syncthreads();

        // === S = Q @ K^T (logits already in log2 domain) ===
        float s[8][4];
#pragma unroll
        for (int j = 0; j < 8; j++)
#pragma unroll
            for (int q = 0; q < 4; q++) s[j][q] = 0.f;

#pragma unroll
        for (int ks = 0; ks < 4; ks++) {
            const uint32_t akb = (uint32_t)(ks * 32) + a_kbb;
            uint32_t qh[4], ql[4];
            ldsm4(sQH + a_rowoff + (akb ^ a_xor), qh);
            ldsm4(sQL + a_rowoff + (akb ^ a_xor), ql);
            const uint32_t kcb = ((uint32_t)(ks * 32) + b_kbb) ^ b_xor;
#pragma unroll
            for (int jp = 0; jp < 4; jp++) {
                const uint32_t roff = (uint32_t)((jp * 16 + b_nr) * 128);
                uint32_t kh[4], kl[4];
                ldsm4(st + roff + kcb, kh);
                ldsm4(st + 8192 + roff + kcb, kl);
                mma16816(s[2 * jp],     qh, kh[0], kh[1]);
                mma16816(s[2 * jp + 1], qh, kh[2], kh[3]);
                mma16816(s[2 * jp],     qh, kl[0], kl[1]);
                mma16816(s[2 * jp + 1], qh, kl[2], kl[3]);
                mma16816(s[2 * jp],     ql, kh[0], kh[1]);
                mma16816(s[2 * jp + 1], ql, kh[2], kh[3]);
            }
        }

        // === online softmax in base 2 ===
        float mx0 = -1e30f, mx1 = -1e30f;
#pragma unroll
        for (int j = 0; j < 8; j++) {
            mx0 = fmaxf(mx0, fmaxf(s[j][0], s[j][1]));
            mx1 = fmaxf(mx1, fmaxf(s[j][2], s[j][3]));
        }
        mx0 = fmaxf(mx0, __shfl_xor_sync(0xffffffffu, mx0, 1));
        mx0 = fmaxf(mx0, __shfl_xor_sync(0xffffffffu, mx0, 2));
        mx1 = fmaxf(mx1, __shfl_xor_sync(0xffffffffu, mx1, 1));
        mx1 = fmaxf(mx1, __shfl_xor_sync(0xffffffffu, mx1, 2));
        const float mn0 = fmaxf(m0, mx0), mn1 = fmaxf(m1, mx1);
        const float al0 = ex2(m0 - mn0), al1 = ex2(m1 - mn1);
#pragma unroll
        for (int j = 0; j < 8; j++) {
            o[j][0] *= al0; o[j][1] *= al0;
            o[j][2] *= al1; o[j][3] *= al1;
        }
        float sum0 = 0.f, sum1 = 0.f;
#pragma unroll
        for (int j = 0; j < 8; j++) {
            s[j][0] = ex2(s[j][0] - mn0);
            s[j][1] = ex2(s[j][1] - mn0);
            s[j][2] = ex2(s[j][2] - mn1);
            s[j][3] = ex2(s[j][3] - mn1);
            sum0 += s[j][0] + s[j][1];
            sum1 += s[j][2] + s[j][3];
        }
        sum0 += __shfl_xor_sync(0xffffffffu, sum0, 1);
        sum0 += __shfl_xor_sync(0xffffffffu, sum0, 2);
        sum1 += __shfl_xor_sync(0xffffffffu, sum1, 1);
        sum1 += __shfl_xor_sync(0xffffffffu, sum1, 2);
        l0 = l0 * al0 + sum0;
        l1 = l1 * al1 + sum1;
        m0 = mn0; m1 = mn1;

        // === O += P @ V (3-term split) ===
#pragma unroll
        for (int kk = 0; kk < 4; kk++) {
            uint32_t aph[4], apl[4];
            pack_split(s[2 * kk][0],     s[2 * kk][1],     aph[0], apl[0]);
            pack_split(s[2 * kk][2],     s[2 * kk][3],     aph[1], apl[1]);
            pack_split(s[2 * kk + 1][0], s[2 * kk + 1][1], aph[2], apl[2]);
            pack_split(s[2 * kk + 1][2], s[2 * kk + 1][3], aph[3], apl[3]);
            const uint32_t vroff = (uint32_t)((kk * 16 + v_r) * 128);
#pragma unroll
            for (int jn = 0; jn < 4; jn++) {
                const uint32_t vcb = ((uint32_t)(jn * 32) + v_cbb) ^ v_xor;
                uint32_t vh[4], vl[4];
                ldsm4t(st + 16384 + vroff + vcb, vh);
                ldsm4t(st + 24576 + vroff + vcb, vl);
                mma16816(o[2 * jn],     aph, vh[0], vh[1]);
                mma16816(o[2 * jn + 1], aph, vh[2], vh[3]);
                mma16816(o[2 * jn],     aph, vl[0], vl[1]);
                mma16816(o[2 * jn + 1], aph, vl[2], vl[3]);
                mma16816(o[2 * jn],     apl, vh[0], vh[1]);
                mma16816(o[2 * jn + 1], apl, vh[2], vh[3]);
            }
        }
        __syncthreads();
    }

    // === epilogue: normalize, pre-split bf16, write ===
    const int gr  = lane >> 2;
    const int cc2 = (lane & 3) * 2;
    const float inv0 = 1.f / l0, inv1 = 1.f / l1;
    const size_t r0 = rowbase + (size_t)(qt * 128 + wm + gr);
#pragma unroll
    for (int j = 0; j < 8; j++) {
        const int col = hcol + j * 8 + cc2;
        uint32_t hp, lp;
        pack_split(o[j][0] * inv0, o[j][1] * inv0, hp, lp);
        *(uint32_t*)&Oh[r0 * EMBED + col] = hp;
        *(uint32_t*)&Ol[r0 * EMBED + col] = lp;
        pack_split(o[j][2] * inv1, o[j][3] * inv1, hp, lp);
        *(uint32_t*)&Oh[(r0 + 8) * EMBED + col] = hp;
        *(uint32_t*)&Ol[(r0 + 8) * EMBED + col] = lp;
    }
}

// ============================================================================
// Launch
// ============================================================================
extern "C" void kernel_launch(void* const* d_in, const int* in_sizes, int n_in,
                              void* d_out, int out_size) {
    const float* x     = (const float*)d_in[0];
    const float* W_qkv = (const float*)d_in[1];
    const float* b_qkv = (const float*)d_in[2];
    const float* W_out = (const float*)d_in[3];
    const float* b_out = (const float*)d_in[4];
    float* out = (float*)d_out;

    __nv_bfloat16 *xh, *xl, *qkvh, *qkvl, *attnh, *attnl;
    __nv_bfloat16 *wq_hi, *wq_lo, *wo_hi, *wo_lo;
    cudaGetSymbolAddress((void**)&xh, g_xh);
    cudaGetSymbolAddress((void**)&xl, g_xl);
    cudaGetSymbolAddress((void**)&qkvh, g_qkvh);
    cudaGetSymbolAddress((void**)&qkvl, g_qkvl);
    cudaGetSymbolAddress((void**)&attnh, g_attnh);
    cudaGetSymbolAddress((void**)&attnl, g_attnl);
    cudaGetSymbolAddress((void**)&wq_hi, g_wq_hi);
    cudaGetSymbolAddress((void**)&wq_lo, g_wq_lo);
    cudaGetSymbolAddress((void**)&wo_hi, g_wo_hi);
    cudaGetSymbolAddress((void**)&wo_lo, g_wo_lo);

    cudaFuncSetAttribute(tc_gemm_192, cudaFuncAttributeMaxDynamicSharedMemorySize, SM_QKV_TOTAL);
    cudaFuncSetAttribute(attn_mma_kernel, cudaFuncAttributeMaxDynamicSharedMemorySize, ATT_SMEM);

    // 0) prep: fused weight transpose+split (wo into padded buffer), x split
    wtrans_split2_kernel<<<dim3(E3 / 32, EMBED / 32, 2), 256>>>(
        W_qkv, wq_hi, wq_lo, W_out, wo_hi, wo_lo);
    fsplit_kernel<<<(M_TOTAL * EMBED / 4) / 256, 256>>>(x, xh, xl);

    // 1) QKV projection (2 CTAs/SM) -> pre-split bf16, Q scaled 0.125*log2e
    tc_gemm_192<<<dim3(E3 / QBN, M_TOTAL / QBM), 192, SM_QKV_TOTAL>>>(
        xh, xl, wq_hi, wq_lo, b_qkv, nullptr, qkvh, qkvl,
        M_TOTAL, E3, EMBED, EMBED, Q_SCALE);

    // 2) Attention (2 CTAs/SM, base-2 softmax) -> pre-split bf16
    dim3 g2(S_LEN / 128, HEADS, BATCH);
    attn_mma_kernel<<<g2, 256, ATT_SMEM>>>(qkvh, qkvl, attnh, attnl);

    // 3) Output projection (2 CTAs/SM, padded N=1056) -> fp32 final output
    tc_gemm_192<<<dim3(N_PAD / QBN, M_TOTAL / QBM), 192, SM_QKV_TOTAL>>>(
        attnh, attnl, wo_hi, wo_lo, b_out, out, nullptr, nullptr,
        M_TOTAL, EMBED, EMBED, 0, 1.0f);
}